// round 13
// baseline (speedup 1.0000x reference)
#include <cuda_runtime.h>
#include <cstdint>

#define BATCH 2
#define SEQ   2048
#define DM    768
#define NH    12
#define DK    64
#define MROWS (BATCH*SEQ)

// Scratch (allocation-free rule: __device__ globals)
__device__ uint16_t g_xh[MROWS*DM],  g_xl[MROWS*DM];
__device__ uint16_t g_qh[MROWS*DM],  g_ql[MROWS*DM];
__device__ uint16_t g_kh[MROWS*DM],  g_kl[MROWS*DM];
__device__ uint16_t g_vth[MROWS*DM], g_vtl[MROWS*DM];
__device__ uint16_t g_ah[MROWS*DM],  g_al[MROWS*DM];
__device__ uint16_t g_wqh[DM*DM], g_wql[DM*DM];
__device__ uint16_t g_wkh[DM*DM], g_wkl[DM*DM];
__device__ uint16_t g_wvh[DM*DM], g_wvl[DM*DM];
__device__ uint16_t g_woh[DM*DM], g_wol[DM*DM];
__device__ float g_p0[MROWS*DM], g_p1[MROWS*DM];   // split-K partials

// ============================================================================
// helpers
// ============================================================================
__device__ __forceinline__ uint32_t smem_u32(const void* p) {
    uint32_t a;
    asm("{ .reg .u64 t; cvta.to.shared.u64 t, %1; cvt.u32.u64 %0, t; }" : "=r"(a) : "l"(p));
    return a;
}
__device__ __forceinline__ uint32_t bfpack(float x, float y) {
    uint32_t r;
    asm("cvt.rn.bf16x2.f32 %0, %1, %2;" : "=r"(r) : "f"(y), "f"(x));
    return r;
}
__device__ __forceinline__ float lo_of(uint32_t p)  { return __uint_as_float(p << 16); }
__device__ __forceinline__ float hi_of(uint32_t p)  { return __uint_as_float(p & 0xffff0000u); }
__device__ __forceinline__ uint16_t bf1(float x) {
    uint16_t u; asm("cvt.rn.bf16.f32 %0, %1;" : "=h"(u) : "f"(x)); return u;
}
__device__ __forceinline__ float bf1v(uint16_t u) { return __uint_as_float(((uint32_t)u) << 16); }

__device__ __forceinline__ void mma16816(float* c, const uint32_t* a, const uint32_t* b) {
    asm volatile(
        "mma.sync.aligned.m16n8k16.row.col.f32.bf16.bf16.f32 "
        "{%0,%1,%2,%3}, {%4,%5,%6,%7}, {%8,%9}, {%0,%1,%2,%3};"
        : "+f"(c[0]), "+f"(c[1]), "+f"(c[2]), "+f"(c[3])
        : "r"(a[0]), "r"(a[1]), "r"(a[2]), "r"(a[3]), "r"(b[0]), "r"(b[1]));
}
__device__ __forceinline__ void ldsm4(uint32_t* r, uint32_t addr) {
    asm volatile("ldmatrix.sync.aligned.m8n8.x4.shared.b16 {%0,%1,%2,%3}, [%4];"
        : "=r"(r[0]), "=r"(r[1]), "=r"(r[2]), "=r"(r[3]) : "r"(addr));
}
#define CP16(dst, src) asm volatile("cp.async.ca.shared.global [%0], [%1], 16;" :: "r"(dst), "l"(src))
#define CP_COMMIT()    asm volatile("cp.async.commit_group;" ::: "memory")
#define CP_WAIT0()     asm volatile("cp.async.wait_group 0;" ::: "memory")

// ============================================================================
// Single fused fp32 -> bf16 hi/lo split over x + 4 weights
// ============================================================================
#define NX4 (MROWS*DM/4)
#define NW4 (DM*DM/4)

__global__ __launch_bounds__(256) void conv_all(const float* __restrict__ x,
                                                const float* __restrict__ wq,
                                                const float* __restrict__ wk,
                                                const float* __restrict__ wv,
                                                const float* __restrict__ wo)
{
    long i = (long)blockIdx.x * blockDim.x + threadIdx.x;
    const float* src; uint16_t *dh, *dl; long j;
    if (i < NX4)                 { src = x;  dh = g_xh;  dl = g_xl;  j = i; }
    else if (i < NX4 + NW4)      { src = wq; dh = g_wqh; dl = g_wql; j = i - NX4; }
    else if (i < NX4 + 2*NW4)    { src = wk; dh = g_wkh; dl = g_wkl; j = i - NX4 - NW4; }
    else if (i < NX4 + 3*NW4)    { src = wv; dh = g_wvh; dl = g_wvl; j = i - NX4 - 2*NW4; }
    else if (i < NX4 + 4*NW4)    { src = wo; dh = g_woh; dl = g_wol; j = i - NX4 - 3*NW4; }
    else return;
    float4 v = ((const float4*)src)[j];
    uint32_t h0 = bfpack(v.x, v.y), h1 = bfpack(v.z, v.w);
    ((uint2*)dh)[j] = make_uint2(h0, h1);
    ((uint2*)dl)[j] = make_uint2(bfpack(v.x - lo_of(h0), v.y - hi_of(h0)),
                                 bfpack(v.z - lo_of(h1), v.w - hi_of(h1)));
}

// ============================================================================
// GEMM core (kc range for split-K): cp.async double-buffered, LDSM, term-major
// ============================================================================
#define SROW 20
#define GST_U32 (128*SROW)
#define GSTAGE_U32 (4*GST_U32)
#define G_SMEM (2*GSTAGE_U32*4)        // 81920 B

__device__ __forceinline__ void gemm_core_bf(const uint16_t* __restrict__ Agh,
                                             const uint16_t* __restrict__ Agl,
                                             const uint16_t* __restrict__ Bgh,
                                             const uint16_t* __restrict__ Bgl,
                                             uint32_t smb, int m0, int n0,
                                             int kc0, int kc1,
                                             int tid, float c[4][4][4])
{
    const int warp = tid >> 5, lane = tid & 31;
    const int wm = warp >> 2, wn = warp & 3;
    const int a_row = lane & 15,                  a_hk = (lane >> 4) * 4;
    const int b_row = ((lane >> 4) << 3) + (lane & 7), b_hk = ((lane >> 3) & 1) * 4;

    auto pre = [&](int kc, int stg) {
#pragma unroll
        for (int u = 0; u < 8; u++) {
            int idx = tid + u * 256;
            int arr = idx >> 9, row = (idx >> 2) & 127, ch = idx & 3;
            const uint16_t* src;
            if      (arr == 0) src = Agh + (long)(m0 + row) * DM + kc * 32 + ch * 8;
            else if (arr == 1) src = Agl + (long)(m0 + row) * DM + kc * 32 + ch * 8;
            else if (arr == 2) src = Bgh + (long)(n0 + row) * DM + kc * 32 + ch * 8;
            else               src = Bgl + (long)(n0 + row) * DM + kc * 32 + ch * 8;
            uint32_t dst = smb + (uint32_t)((stg * 4 + arr) * GST_U32 + row * SROW + ch * 4) * 4;
            CP16(dst, src);
        }
        CP_COMMIT();
    };

    pre(kc0, 0);

    for (int kc = kc0; kc < kc1; kc++) {
        const int stg = (kc - kc0) & 1;
        CP_WAIT0();
        __syncthreads();
        if (kc + 1 < kc1) pre(kc + 1, stg ^ 1);

        const uint32_t sAh = smb + (uint32_t)(stg * GSTAGE_U32) * 4;
        const uint32_t sAl = sAh + GST_U32 * 4;
        const uint32_t sBh = sAh + 2 * GST_U32 * 4;
        const uint32_t sBl = sAh + 3 * GST_U32 * 4;

#pragma unroll
        for (int ks = 0; ks < 2; ks++) {
            uint32_t bh[4][2], bl[4][2];
#pragma unroll
            for (int p = 0; p < 2; p++) {
                uint32_t off = (uint32_t)((wn * 32 + p * 16 + b_row) * SROW + ks * 8 + b_hk) * 4;
                uint32_t rr[4];
                ldsm4(rr, sBh + off);
                bh[2*p][0] = rr[0]; bh[2*p][1] = rr[1];
                bh[2*p+1][0] = rr[2]; bh[2*p+1][1] = rr[3];
                ldsm4(rr, sBl + off);
                bl[2*p][0] = rr[0]; bl[2*p][1] = rr[1];
                bl[2*p+1][0] = rr[2]; bl[2*p+1][1] = rr[3];
            }
#pragma unroll
            for (int mt = 0; mt < 4; mt++) {
                uint32_t off = (uint32_t)((wm * 64 + mt * 16 + a_row) * SROW + ks * 8 + a_hk) * 4;
                uint32_t ah[4], al[4];
                ldsm4(ah, sAh + off);
                ldsm4(al, sAl + off);
#pragma unroll
                for (int nt = 0; nt < 4; nt++) mma16816(c[mt][nt], ah, bh[nt]);
#pragma unroll
                for (int nt = 0; nt < 4; nt++) mma16816(c[mt][nt], al, bh[nt]);
#pragma unroll
                for (int nt = 0; nt < 4; nt++) mma16816(c[mt][nt], ah, bl[nt]);
            }
        }
    }
}

// ============================================================================
// Fused QKV projection
// ============================================================================
__global__ __launch_bounds__(256, 2) void gemm_qkv()
{
    extern __shared__ __align__(16) uint32_t dsm[];
    const uint32_t smb = smem_u32(dsm);

    const int tid  = threadIdx.x;
    const int warp = tid >> 5, lane = tid & 31;
    const int g = lane >> 2, t = lane & 3;
    const int wm = warp >> 2, wn = warp & 3;
    const int m0 = blockIdx.y * 128, n0 = blockIdx.x * 128;
    const int z = blockIdx.z;
    const uint16_t* Bgh = (z == 0) ? g_wqh : ((z == 1) ? g_wkh : g_wvh);
    const uint16_t* Bgl = (z == 0) ? g_wql : ((z == 1) ? g_wkl : g_wvl);

    float c[4][4][4];
#pragma unroll
    for (int i = 0; i < 4; i++)
#pragma unroll
        for (int j = 0; j < 4; j++)
#pragma unroll
            for (int r = 0; r < 4; r++) c[i][j][r] = 0.f;

    gemm_core_bf(g_xh, g_xl, Bgh, Bgl, smb, m0, n0, 0, DM/32, tid, c);

    if (z < 2) {
        uint16_t* Hh = (z == 0) ? g_qh : g_kh;
        uint16_t* Hl = (z == 0) ? g_ql : g_kl;
        const float sc = (z == 0) ? 0.125f : 1.0f;
#pragma unroll
        for (int mt = 0; mt < 4; mt++) {
#pragma unroll
            for (int nt = 0; nt < 4; nt++) {
                int row = m0 + wm * 64 + mt * 16 + g;
                int col = n0 + wn * 32 + nt * 8 + 2 * t;
                float x0 = c[mt][nt][0] * sc, x1 = c[mt][nt][1] * sc;
                float x2 = c[mt][nt][2] * sc, x3 = c[mt][nt][3] * sc;
                uint32_t h0 = bfpack(x0, x1), h1 = bfpack(x2, x3);
                *(uint32_t*)&Hh[(long)row * DM + col]       = h0;
                *(uint32_t*)&Hl[(long)row * DM + col]       = bfpack(x0 - lo_of(h0), x1 - hi_of(h0));
                *(uint32_t*)&Hh[(long)(row + 8) * DM + col] = h1;
                *(uint32_t*)&Hl[(long)(row + 8) * DM + col] = bfpack(x2 - lo_of(h1), x3 - hi_of(h1));
            }
        }
    } else {
        uint16_t* st = (uint16_t*)dsm;
        const int b = m0 / SEQ, s0 = m0 % SEQ;
#pragma unroll
        for (int pass = 0; pass < 2; pass++) {
            __syncthreads();
#pragma unroll
            for (int mt = 0; mt < 4; mt++)
#pragma unroll
                for (int nt = 0; nt < 4; nt++)
#pragma unroll
                    for (int r = 0; r < 4; r++) {
                        float cv = c[mt][nt][r];
                        uint16_t hv = bf1(cv);
                        uint16_t val = pass ? bf1(cv - bf1v(hv)) : hv;
                        int rowl = wm * 64 + mt * 16 + g + ((r >> 1) ? 8 : 0);
                        int coll = wn * 32 + nt * 8 + 2 * t + (r & 1);
                        st[coll * 136 + rowl] = val;
                    }
            __syncthreads();
            uint16_t* dstb = pass ? g_vtl : g_vth;
#pragma unroll
            for (int u = 0; u < 8; u++) {
                int idx = tid + u * 256;
                int dl128 = idx >> 4, ch = idx & 15;
                uint4 v = *(const uint4*)&st[dl128 * 136 + ch * 8];
                int colg = n0 + dl128;
                int hh = colg >> 6, dl = colg & 63;
                *(uint4*)&dstb[((long)((b * NH + hh) * DK + dl)) * SEQ + s0 + ch * 8] = v;
            }
        }
    }
}

// ============================================================================
// Output projection: split-K2 into partials, then add
// ============================================================================
__global__ __launch_bounds__(256, 2) void gemm_out_sk()
{
    extern __shared__ __align__(16) uint32_t dsm[];
    const uint32_t smb = smem_u32(dsm);

    const int tid  = threadIdx.x;
    const int warp = tid >> 5, lane = tid & 31;
    const int g = lane >> 2, t = lane & 3;
    const int wm = warp >> 2, wn = warp & 3;
    const int m0 = blockIdx.y * 128, n0 = blockIdx.x * 128;
    const int z = blockIdx.z;
    float* P = z ? g_p1 : g_p0;

    float c[4][4][4];
#pragma unroll
    for (int i = 0; i < 4; i++)
#pragma unroll
        for (int j = 0; j < 4; j++)
#pragma unroll
            for (int r = 0; r < 4; r++) c[i][j][r] = 0.f;

    gemm_core_bf(g_ah, g_al, g_woh, g_wol, smb, m0, n0, z * 12, (z + 1) * 12, tid, c);

#pragma unroll
    for (int mt = 0; mt < 4; mt++) {
#pragma unroll
        for (int nt = 0; nt < 4; nt++) {
            int row = m0 + wm * 64 + mt * 16 + g;
            int col = n0 + wn * 32 + nt * 8 + t * 2;
            *(float2*)&P[(long)row * DM + col]       = make_float2(c[mt][nt][0], c[mt][nt][1]);
            *(float2*)&P[(long)(row + 8) * DM + col] = make_float2(c[mt][nt][2], c[mt][nt][3]);
        }
    }
}

__global__ __launch_bounds__(256) void add_out(float* __restrict__ out)
{
    int i = blockIdx.x * blockDim.x + threadIdx.x;
    if (i < NX4) {
        float4 a = ((const float4*)g_p0)[i];
        float4 b = ((const float4*)g_p1)[i];
        ((float4*)out)[i] = make_float4(a.x + b.x, a.y + b.y, a.z + b.z, a.w + b.w);
    }
}

// ============================================================================
// Flash attention: Q in smem (2 CTAs/SM), cp.async double-buffered K/V, LDSM.
// BQ=128, BK=64. grid = (SEQ/128, NH, BATCH), longest-qb first.
// ============================================================================
#define VS 36
#define ARR_U32 (64*VS)
#define STAGE_U32 (4*ARR_U32)
#define QOFF_U32 (2*STAGE_U32)
#define QARR_U32 (128*VS)
#define FL_SMEM ((2*STAGE_U32 + 2*QARR_U32)*4)   // 73728 + 36864 = 110592 B

__global__ __launch_bounds__(256, 2) void flash_mma()
{
    extern __shared__ __align__(16) uint32_t fsm[];
    const uint32_t smb = smem_u32(fsm);

    const int tid  = threadIdx.x;
    const int warp = tid >> 5, lane = tid & 31;
    const int g = lane >> 2, t = lane & 3;
    const int qb = gridDim.x - 1 - blockIdx.x;    // longest CTAs first
    const int h = blockIdx.y, b = blockIdx.z;
    const int q0 = qb * 128;
    const int headoff = h * DK;
    const long rowbase = (long)(b * SEQ + q0 + warp * 16);
    const long vtbase  = (long)((b * NH + h) * DK) * SEQ;
    const float NEG_INF = __int_as_float(0xff800000);

    // B-style fragment lane addressing (K, V^T)
    const int f_row = ((lane >> 4) << 3) + (lane & 7);
    const int f_hk  = ((lane >> 3) & 1) * 4;
    // A-style fragment lane addressing (Q)
    const uint32_t qbase = smb + (uint32_t)(QOFF_U32 + (warp * 16 + (lane & 15)) * VS + (lane >> 4) * 4) * 4;

    const int jmax = 2 * (qb + 1);

    // ---- Q tile -> smem (hi/lo), included in first cp.async group ----
#pragma unroll
    for (int u = 0; u < 8; u++) {
        int idx = tid + u * 256;            // 2048 chunks: 2 arrays x 128 rows x 8
        int arr = idx >> 10, rem = idx & 1023;
        int row = rem >> 3, ch = rem & 7;
        const uint16_t* src = (arr ? g_ql : g_qh) + (long)(b * SEQ + q0 + row) * DM + headoff + ch * 8;
        uint32_t dst = smb + (uint32_t)(QOFF_U32 + arr * QARR_U32 + row * VS) * 4 + ch * 16;
        CP16(dst, src);
    }

    auto prefetch = [&](int jb, int stg) {
        const int ch = tid & 7;
#pragma unroll
        for (int u = 0; u < 8; u++) {
            int arr = u >> 1;
            int r2  = ((u & 1) << 5) + (tid >> 3);
            const uint16_t* src;
            long koff = (long)(b * SEQ + jb * 64 + r2) * DM + headoff + ch * 8;
            long voff = vtbase + (long)r2 * SEQ + jb * 64 + ch * 8;
            if      (arr == 0) src = g_kh  + koff;
            else if (arr == 1) src = g_kl  + koff;
            else if (arr == 2) src = g_vth + voff;
            else               src = g_vtl + voff;
            uint32_t dst = smb + (uint32_t)(stg * STAGE_U32 + arr * ARR_U32 + r2 * VS) * 4 + ch * 16;
            CP16(dst, src);
        }
        CP_COMMIT();
    };

    prefetch(0, 0);   // commits Q chunks + KV stage 0

    float m[2] = {NEG_INF, NEG_INF}, l[2] = {0.f, 0.f};
    float o[8][4];
#pragma unroll
    for (int dt = 0; dt < 8; dt++)
#pragma unroll
        for (int r = 0; r < 4; r++) o[dt][r] = 0.f;

    for (int jb = 0; jb < jmax; jb++) {
        const int stg = jb & 1;
        CP_WAIT0();
        __syncthreads();
        if (jb + 1 < jmax) prefetch(jb + 1, stg ^ 1);

        const uint32_t sK  = smb + (uint32_t)(stg * STAGE_U32) * 4;
        const uint32_t sKl = sK + ARR_U32 * 4;
        const uint32_t sVh = sK + 2 * ARR_U32 * 4;
        const uint32_t sVl = sK + 3 * ARR_U32 * 4;

        // ---- S = Q K^T ----
        float s[8][4];
#pragma unroll
        for (int nt = 0; nt < 8; nt++)
#pragma unroll
            for (int r = 0; r < 4; r++) s[nt][r] = 0.f;
#pragma unroll
        for (int ks = 0; ks < 4; ks++) {
            uint32_t qhf[4], qlf[4];
            ldsm4(qhf, qbase + ks * 32);
            ldsm4(qlf, qbase + QARR_U32 * 4 + ks * 32);
#pragma unroll
            for (int pp = 0; pp < 2; pp++) {
                uint32_t off0 = (uint32_t)(((2*pp)   * 16 + f_row) * VS + ks * 8 + f_hk) * 4;
                uint32_t off1 = (uint32_t)(((2*pp+1) * 16 + f_row) * VS + ks * 8 + f_hk) * 4;
                uint32_t kh0[4], kl0[4], kh1[4], kl1[4];
                ldsm4(kh0, sK  + off0);
                ldsm4(kl0, sKl + off0);
                ldsm4(kh1, sK  + off1);
                ldsm4(kl1, sKl + off1);
                float* s0 = s[4*pp]; float* s1 = s[4*pp+1];
                float* s2 = s[4*pp+2]; float* s3 = s[4*pp+3];
                mma16816(s0, qhf, kh0); mma16816(s1, qhf, kh0 + 2);
                mma16816(s2, qhf, kh1); mma16816(s3, qhf, kh1 + 2);
                mma16816(s0, qlf, kh0); mma16816(s1, qlf, kh0 + 2);
                mma16816(s2, qlf, kh1); mma16816(s3, qlf, kh1 + 2);
                mma16816(s0, qhf, kl0); mma16816(s1, qhf, kl0 + 2);
                mma16816(s2, qhf, kl1); mma16816(s3, qhf, kl1 + 2);
            }
        }

        // ---- causal mask ----
        if (jb >= 2 * qb) {
#pragma unroll
            for (int nt = 0; nt < 8; nt++)
#pragma unroll
                for (int r = 0; r < 4; r++) {
                    int key = jb * 64 + nt * 8 + 2 * t + (r & 1);
                    int qr  = q0 + warp * 16 + g + ((r >> 1) ? 8 : 0);
                    if (key > qr) s[nt][r] = NEG_INF;
                }
        }

        // ---- online softmax ----
        float mx0 = NEG_INF, mx1 = NEG_INF;
#pragma unroll
        for (int nt = 0; nt < 8; nt++) {
            mx0 = fmaxf(mx0, fmaxf(s[nt][0], s[nt][1]));
            mx1 = fmaxf(mx1, fmaxf(s[nt][2], s[nt][3]));
        }
        mx0 = fmaxf(mx0, __shfl_xor_sync(0xffffffffu, mx0, 1));
        mx0 = fmaxf(mx0, __shfl_xor_sync(0xffffffffu, mx0, 2));
        mx1 = fmaxf(mx1, __shfl_xor_sync(0xffffffffu, mx1, 1));
        mx1 = fmaxf(mx1, __shfl_xor_sync(0xffffffffu, mx1, 2));
        float mn0 = fmaxf(m[0], mx0), mn1 = fmaxf(m[1], mx1);
        float al0 = __expf(m[0] - mn0), al1 = __expf(m[1] - mn1);
        m[0] = mn0; m[1] = mn1;
        float ps0 = 0.f, ps1 = 0.f;
#pragma unroll
        for (int nt = 0; nt < 8; nt++) {
            s[nt][0] = __expf(s[nt][0] - mn0); ps0 += s[nt][0];
            s[nt][1] = __expf(s[nt][1] - mn0); ps0 += s[nt][1];
            s[nt][2] = __expf(s[nt][2] - mn1); ps1 += s[nt][2];
            s[nt][3] = __expf(s[nt][3] - mn1); ps1 += s[nt][3];
        }
        ps0 += __shfl_xor_sync(0xffffffffu, ps0, 1);
        ps0 += __shfl_xor_sync(0xffffffffu, ps0, 2);
        ps1 += __shfl_xor_sync(0xffffffffu, ps1, 1);
        ps1 += __shfl_xor_sync(0xffffffffu, ps1, 2);
        l[0] = l[0] * al0 + ps0;
        l[1] = l[1] * al1 + ps1;
#pragma unroll
        for (int dt = 0; dt < 8; dt++) {
            o[dt][0] *= al0; o[dt][1] *= al0;
            o[dt][2] *= al1; o[dt][3] *= al1;
        }

        // ---- O += P V ----
#pragma unroll
        for (int kt = 0; kt < 4; kt++) {
            uint32_t ph[4], pl[4];
            ph[0] = bfpack(s[2*kt][0],   s[2*kt][1]);
            ph[1] = bfpack(s[2*kt][2],   s[2*kt][3]);
            ph[2] = bfpack(s[2*kt+1][0], s[2*kt+1][1]);
            ph[3] = bfpack(s[2*kt+1][2], s[2*kt+1][3]);
            pl[0] = bfpack(s[2*kt][0]   - lo_of(ph[0]), s[2*kt][1]   - hi_of(ph[0]));
            pl[1] = bfpack(s[2*kt][2]   - lo_of(ph[1]), s[2*kt][3]   - hi_of(ph[1]));
            pl[2] = bfpack(s[2*kt+1][0] - lo_of(ph[2]), s[2*kt+1][1] - hi_of(ph[2]));
            pl[3] = bfpack(s[2*kt+1][2] - lo_of(ph[3]), s[2*kt+1][3] - hi_of(ph[3]));
#pragma unroll
            for (int pp = 0; pp < 2; pp++) {
                uint32_t off0 = (uint32_t)(((2*pp)   * 16 + f_row) * VS + kt * 8 + f_hk) * 4;
                uint32_t off1 = (uint32_t)(((2*pp+1) * 16 + f_row) * VS + kt * 8 + f_hk) * 4;
                uint32_t vh0[4], vl0[4], vh1[4], vl1[4];
                ldsm4(vh0, sVh + off0);
                ldsm4(vl0, sVl + off0);
                ldsm4(vh1, sVh + off1);
                ldsm4(vl1, sVl + off1);
                float* o0 = o[4*pp]; float* o1 = o[4*pp+1];
                float* o2 = o[4*pp+2]; float* o3 = o[4*pp+3];
                mma16816(o0, ph, vh0); mma16816(o1, ph, vh0 + 2);
                mma16816(o2, ph, vh1); mma16816(o3, ph, vh1 + 2);
                mma16816(o0, pl, vh0); mma16816(o1, pl, vh0 + 2);
                mma16816(o2, pl, vh1); mma16816(o3, pl, vh1 + 2);
                mma16816(o0, ph, vl0); mma16816(o1, ph, vl0 + 2);
                mma16816(o2, ph, vl1); mma16816(o3, ph, vl1 + 2);
            }
        }
    }

    // ---- epilogue: write bf16 hi/lo for the output projection ----
    float inv0 = 1.f / l[0], inv1 = 1.f / l[1];
#pragma unroll
    for (int dt = 0; dt < 8; dt++) {
        int col = headoff + dt * 8 + 2 * t;
        float a0 = o[dt][0] * inv0, a1 = o[dt][1] * inv0;
        float a2 = o[dt][2] * inv1, a3 = o[dt][3] * inv1;
        uint32_t h0 = bfpack(a0, a1), h1 = bfpack(a2, a3);
        *(uint32_t*)&g_ah[(rowbase + g) * DM + col]     = h0;
        *(uint32_t*)&g_al[(rowbase + g) * DM + col]     = bfpack(a0 - lo_of(h0), a1 - hi_of(h0));
        *(uint32_t*)&g_ah[(rowbase + g + 8) * DM + col] = h1;
        *(uint32_t*)&g_al[(rowbase + g + 8) * DM + col] = bfpack(a2 - lo_of(h1), a3 - hi_of(h1));
    }
}

// ---------------------------------------------------------------------------
extern "C" void kernel_launch(void* const* d_in, const int* in_sizes, int n_in,
                              void* d_out, int out_size)
{
    const float* x  = (const float*)d_in[0];
    const float* wq = (const float*)d_in[1];
    const float* wk = (const float*)d_in[2];
    const float* wv = (const float*)d_in[3];
    const float* wo = (const float*)d_in[4];
    float* out = (float*)d_out;

    cudaFuncSetAttribute(flash_mma,   cudaFuncAttributeMaxDynamicSharedMemorySize, FL_SMEM);
    cudaFuncSetAttribute(gemm_qkv,    cudaFuncAttributeMaxDynamicSharedMemorySize, G_SMEM);
    cudaFuncSetAttribute(gemm_out_sk, cudaFuncAttributeMaxDynamicSharedMemorySize, G_SMEM);

    const long ntot = NX4 + 4L * NW4;
    conv_all<<<(int)((ntot + 255) / 256), 256>>>(x, wq, wk, wv, wo);

    gemm_qkv<<<dim3(DM / 128, MROWS / 128, 3), 256, G_SMEM>>>();
    flash_mma<<<dim3(SEQ / 128, NH, BATCH), 256, FL_SMEM>>>();
    gemm_out_sk<<<dim3(DM / 128, MROWS / 128, 2), 256, G_SMEM>>>();
    add_out<<<(NX4 + 255) / 256, 256>>>(out);
}

// round 14
// speedup vs baseline: 1.0604x; 1.0604x over previous
#include <cuda_runtime.h>
#include <cstdint>

#define BATCH 2
#define SEQ   2048
#define DM    768
#define NH    12
#define DK    64
#define MROWS (BATCH*SEQ)

// Scratch (allocation-free rule: __device__ globals)
__device__ uint16_t g_xh[MROWS*DM],  g_xl[MROWS*DM];
__device__ uint16_t g_qh[MROWS*DM],  g_ql[MROWS*DM];
__device__ uint16_t g_kh[MROWS*DM],  g_kl[MROWS*DM];
__device__ uint16_t g_vth[MROWS*DM], g_vtl[MROWS*DM];
__device__ uint16_t g_ah[MROWS*DM],  g_al[MROWS*DM];
__device__ uint16_t g_wqh[DM*DM], g_wql[DM*DM];
__device__ uint16_t g_wkh[DM*DM], g_wkl[DM*DM];
__device__ uint16_t g_wvh[DM*DM], g_wvl[DM*DM];
__device__ uint16_t g_woh[DM*DM], g_wol[DM*DM];
__device__ float g_p0[MROWS*DM], g_p1[MROWS*DM];   // split-K partials

// ============================================================================
// helpers
// ============================================================================
__device__ __forceinline__ uint32_t smem_u32(const void* p) {
    uint32_t a;
    asm("{ .reg .u64 t; cvta.to.shared.u64 t, %1; cvt.u32.u64 %0, t; }" : "=r"(a) : "l"(p));
    return a;
}
__device__ __forceinline__ uint32_t bfpack(float x, float y) {
    uint32_t r;
    asm("cvt.rn.bf16x2.f32 %0, %1, %2;" : "=r"(r) : "f"(y), "f"(x));
    return r;
}
__device__ __forceinline__ float lo_of(uint32_t p)  { return __uint_as_float(p << 16); }
__device__ __forceinline__ float hi_of(uint32_t p)  { return __uint_as_float(p & 0xffff0000u); }
__device__ __forceinline__ uint16_t bf1(float x) {
    uint16_t u; asm("cvt.rn.bf16.f32 %0, %1;" : "=h"(u) : "f"(x)); return u;
}
__device__ __forceinline__ float bf1v(uint16_t u) { return __uint_as_float(((uint32_t)u) << 16); }

__device__ __forceinline__ void mma16816(float* c, const uint32_t* a, const uint32_t* b) {
    asm volatile(
        "mma.sync.aligned.m16n8k16.row.col.f32.bf16.bf16.f32 "
        "{%0,%1,%2,%3}, {%4,%5,%6,%7}, {%8,%9}, {%0,%1,%2,%3};"
        : "+f"(c[0]), "+f"(c[1]), "+f"(c[2]), "+f"(c[3])
        : "r"(a[0]), "r"(a[1]), "r"(a[2]), "r"(a[3]), "r"(b[0]), "r"(b[1]));
}
__device__ __forceinline__ void ldsm4(uint32_t* r, uint32_t addr) {
    asm volatile("ldmatrix.sync.aligned.m8n8.x4.shared.b16 {%0,%1,%2,%3}, [%4];"
        : "=r"(r[0]), "=r"(r[1]), "=r"(r[2]), "=r"(r[3]) : "r"(addr));
}
#define CP16(dst, src) asm volatile("cp.async.ca.shared.global [%0], [%1], 16;" :: "r"(dst), "l"(src))
#define CP_COMMIT()    asm volatile("cp.async.commit_group;" ::: "memory")
#define CP_WAIT0()     asm volatile("cp.async.wait_group 0;" ::: "memory")

// ============================================================================
// Single fused fp32 -> bf16 hi/lo split over x + 4 weights
// ============================================================================
#define NX4 (MROWS*DM/4)
#define NW4 (DM*DM/4)

__global__ __launch_bounds__(256) void conv_all(const float* __restrict__ x,
                                                const float* __restrict__ wq,
                                                const float* __restrict__ wk,
                                                const float* __restrict__ wv,
                                                const float* __restrict__ wo)
{
    long i = (long)blockIdx.x * blockDim.x + threadIdx.x;
    const float* src; uint16_t *dh, *dl; long j;
    if (i < NX4)                 { src = x;  dh = g_xh;  dl = g_xl;  j = i; }
    else if (i < NX4 + NW4)      { src = wq; dh = g_wqh; dl = g_wql; j = i - NX4; }
    else if (i < NX4 + 2*NW4)    { src = wk; dh = g_wkh; dl = g_wkl; j = i - NX4 - NW4; }
    else if (i < NX4 + 3*NW4)    { src = wv; dh = g_wvh; dl = g_wvl; j = i - NX4 - 2*NW4; }
    else if (i < NX4 + 4*NW4)    { src = wo; dh = g_woh; dl = g_wol; j = i - NX4 - 3*NW4; }
    else return;
    float4 v = ((const float4*)src)[j];
    uint32_t h0 = bfpack(v.x, v.y), h1 = bfpack(v.z, v.w);
    ((uint2*)dh)[j] = make_uint2(h0, h1);
    ((uint2*)dl)[j] = make_uint2(bfpack(v.x - lo_of(h0), v.y - hi_of(h0)),
                                 bfpack(v.z - lo_of(h1), v.w - hi_of(h1)));
}

// ============================================================================
// GEMM core (kc range for split-K): cp.async double-buffered, LDSM, term-major
// ============================================================================
#define SROW 20
#define GST_U32 (128*SROW)
#define GSTAGE_U32 (4*GST_U32)
#define G_SMEM (2*GSTAGE_U32*4)        // 81920 B

__device__ __forceinline__ void gemm_core_bf(const uint16_t* __restrict__ Agh,
                                             const uint16_t* __restrict__ Agl,
                                             const uint16_t* __restrict__ Bgh,
                                             const uint16_t* __restrict__ Bgl,
                                             uint32_t smb, int m0, int n0,
                                             int kc0, int kc1,
                                             int tid, float c[4][4][4])
{
    const int warp = tid >> 5, lane = tid & 31;
    const int wm = warp >> 2, wn = warp & 3;
    const int a_row = lane & 15,                  a_hk = (lane >> 4) * 4;
    const int b_row = ((lane >> 4) << 3) + (lane & 7), b_hk = ((lane >> 3) & 1) * 4;

    auto pre = [&](int kc, int stg) {
#pragma unroll
        for (int u = 0; u < 8; u++) {
            int idx = tid + u * 256;
            int arr = idx >> 9, row = (idx >> 2) & 127, ch = idx & 3;
            const uint16_t* src;
            if      (arr == 0) src = Agh + (long)(m0 + row) * DM + kc * 32 + ch * 8;
            else if (arr == 1) src = Agl + (long)(m0 + row) * DM + kc * 32 + ch * 8;
            else if (arr == 2) src = Bgh + (long)(n0 + row) * DM + kc * 32 + ch * 8;
            else               src = Bgl + (long)(n0 + row) * DM + kc * 32 + ch * 8;
            uint32_t dst = smb + (uint32_t)((stg * 4 + arr) * GST_U32 + row * SROW + ch * 4) * 4;
            CP16(dst, src);
        }
        CP_COMMIT();
    };

    pre(kc0, 0);

    for (int kc = kc0; kc < kc1; kc++) {
        const int stg = (kc - kc0) & 1;
        CP_WAIT0();
        __syncthreads();
        if (kc + 1 < kc1) pre(kc + 1, stg ^ 1);

        const uint32_t sAh = smb + (uint32_t)(stg * GSTAGE_U32) * 4;
        const uint32_t sAl = sAh + GST_U32 * 4;
        const uint32_t sBh = sAh + 2 * GST_U32 * 4;
        const uint32_t sBl = sAh + 3 * GST_U32 * 4;

#pragma unroll
        for (int ks = 0; ks < 2; ks++) {
            uint32_t bh[4][2], bl[4][2];
#pragma unroll
            for (int p = 0; p < 2; p++) {
                uint32_t off = (uint32_t)((wn * 32 + p * 16 + b_row) * SROW + ks * 8 + b_hk) * 4;
                uint32_t rr[4];
                ldsm4(rr, sBh + off);
                bh[2*p][0] = rr[0]; bh[2*p][1] = rr[1];
                bh[2*p+1][0] = rr[2]; bh[2*p+1][1] = rr[3];
                ldsm4(rr, sBl + off);
                bl[2*p][0] = rr[0]; bl[2*p][1] = rr[1];
                bl[2*p+1][0] = rr[2]; bl[2*p+1][1] = rr[3];
            }
#pragma unroll
            for (int mt = 0; mt < 4; mt++) {
                uint32_t off = (uint32_t)((wm * 64 + mt * 16 + a_row) * SROW + ks * 8 + a_hk) * 4;
                uint32_t ah[4], al[4];
                ldsm4(ah, sAh + off);
                ldsm4(al, sAl + off);
#pragma unroll
                for (int nt = 0; nt < 4; nt++) mma16816(c[mt][nt], ah, bh[nt]);
#pragma unroll
                for (int nt = 0; nt < 4; nt++) mma16816(c[mt][nt], al, bh[nt]);
#pragma unroll
                for (int nt = 0; nt < 4; nt++) mma16816(c[mt][nt], ah, bl[nt]);
            }
        }
    }
}

// ============================================================================
// Fused QKV projection
// ============================================================================
__global__ __launch_bounds__(256, 2) void gemm_qkv()
{
    extern __shared__ __align__(16) uint32_t dsm[];
    const uint32_t smb = smem_u32(dsm);

    const int tid  = threadIdx.x;
    const int warp = tid >> 5, lane = tid & 31;
    const int g = lane >> 2, t = lane & 3;
    const int wm = warp >> 2, wn = warp & 3;
    const int m0 = blockIdx.y * 128, n0 = blockIdx.x * 128;
    const int z = blockIdx.z;
    const uint16_t* Bgh = (z == 0) ? g_wqh : ((z == 1) ? g_wkh : g_wvh);
    const uint16_t* Bgl = (z == 0) ? g_wql : ((z == 1) ? g_wkl : g_wvl);

    float c[4][4][4];
#pragma unroll
    for (int i = 0; i < 4; i++)
#pragma unroll
        for (int j = 0; j < 4; j++)
#pragma unroll
            for (int r = 0; r < 4; r++) c[i][j][r] = 0.f;

    gemm_core_bf(g_xh, g_xl, Bgh, Bgl, smb, m0, n0, 0, DM/32, tid, c);

    if (z < 2) {
        uint16_t* Hh = (z == 0) ? g_qh : g_kh;
        uint16_t* Hl = (z == 0) ? g_ql : g_kl;
        const float sc = (z == 0) ? 0.125f : 1.0f;
#pragma unroll
        for (int mt = 0; mt < 4; mt++) {
#pragma unroll
            for (int nt = 0; nt < 4; nt++) {
                int row = m0 + wm * 64 + mt * 16 + g;
                int col = n0 + wn * 32 + nt * 8 + 2 * t;
                float x0 = c[mt][nt][0] * sc, x1 = c[mt][nt][1] * sc;
                float x2 = c[mt][nt][2] * sc, x3 = c[mt][nt][3] * sc;
                uint32_t h0 = bfpack(x0, x1), h1 = bfpack(x2, x3);
                *(uint32_t*)&Hh[(long)row * DM + col]       = h0;
                *(uint32_t*)&Hl[(long)row * DM + col]       = bfpack(x0 - lo_of(h0), x1 - hi_of(h0));
                *(uint32_t*)&Hh[(long)(row + 8) * DM + col] = h1;
                *(uint32_t*)&Hl[(long)(row + 8) * DM + col] = bfpack(x2 - lo_of(h1), x3 - hi_of(h1));
            }
        }
    } else {
        uint16_t* st = (uint16_t*)dsm;
        const int b = m0 / SEQ, s0 = m0 % SEQ;
#pragma unroll
        for (int pass = 0; pass < 2; pass++) {
            __syncthreads();
#pragma unroll
            for (int mt = 0; mt < 4; mt++)
#pragma unroll
                for (int nt = 0; nt < 4; nt++)
#pragma unroll
                    for (int r = 0; r < 4; r++) {
                        float cv = c[mt][nt][r];
                        uint16_t hv = bf1(cv);
                        uint16_t val = pass ? bf1(cv - bf1v(hv)) : hv;
                        int rowl = wm * 64 + mt * 16 + g + ((r >> 1) ? 8 : 0);
                        int coll = wn * 32 + nt * 8 + 2 * t + (r & 1);
                        st[coll * 136 + rowl] = val;
                    }
            __syncthreads();
            uint16_t* dstb = pass ? g_vtl : g_vth;
#pragma unroll
            for (int u = 0; u < 8; u++) {
                int idx = tid + u * 256;
                int dl128 = idx >> 4, ch = idx & 15;
                uint4 v = *(const uint4*)&st[dl128 * 136 + ch * 8];
                int colg = n0 + dl128;
                int hh = colg >> 6, dl = colg & 63;
                *(uint4*)&dstb[((long)((b * NH + hh) * DK + dl)) * SEQ + s0 + ch * 8] = v;
            }
        }
    }
}

// ============================================================================
// Output projection: split-K2 into partials, then add
// ============================================================================
__global__ __launch_bounds__(256, 2) void gemm_out_sk()
{
    extern __shared__ __align__(16) uint32_t dsm[];
    const uint32_t smb = smem_u32(dsm);

    const int tid  = threadIdx.x;
    const int warp = tid >> 5, lane = tid & 31;
    const int g = lane >> 2, t = lane & 3;
    const int wm = warp >> 2, wn = warp & 3;
    const int m0 = blockIdx.y * 128, n0 = blockIdx.x * 128;
    const int z = blockIdx.z;
    float* P = z ? g_p1 : g_p0;

    float c[4][4][4];
#pragma unroll
    for (int i = 0; i < 4; i++)
#pragma unroll
        for (int j = 0; j < 4; j++)
#pragma unroll
            for (int r = 0; r < 4; r++) c[i][j][r] = 0.f;

    gemm_core_bf(g_ah, g_al, g_woh, g_wol, smb, m0, n0, z * 12, (z + 1) * 12, tid, c);

#pragma unroll
    for (int mt = 0; mt < 4; mt++) {
#pragma unroll
        for (int nt = 0; nt < 4; nt++) {
            int row = m0 + wm * 64 + mt * 16 + g;
            int col = n0 + wn * 32 + nt * 8 + t * 2;
            *(float2*)&P[(long)row * DM + col]       = make_float2(c[mt][nt][0], c[mt][nt][1]);
            *(float2*)&P[(long)(row + 8) * DM + col] = make_float2(c[mt][nt][2], c[mt][nt][3]);
        }
    }
}

__global__ __launch_bounds__(256) void add_out(float* __restrict__ out)
{
    int i = blockIdx.x * blockDim.x + threadIdx.x;
    if (i < NX4) {
        float4 a = ((const float4*)g_p0)[i];
        float4 b = ((const float4*)g_p1)[i];
        ((float4*)out)[i] = make_float4(a.x + b.x, a.y + b.y, a.z + b.z, a.w + b.w);
    }
}

// ============================================================================
// Flash attention (R12-proven version): Q fragments in registers, cp.async
// double-buffered K/V, LDSM, pair-interleaved mma, longest-qb first.
// BQ=128, BK=64. grid = (SEQ/128, NH, BATCH).
// ============================================================================
#define VS 36
#define ARR_U32 (64*VS)
#define STAGE_U32 (4*ARR_U32)
#define FL_SMEM (2*STAGE_U32*4)         // 73728 B

__global__ __launch_bounds__(256) void flash_mma()
{
    extern __shared__ __align__(16) uint32_t fsm[];
    const uint32_t smb = smem_u32(fsm);

    const int tid  = threadIdx.x;
    const int warp = tid >> 5, lane = tid & 31;
    const int g = lane >> 2, t = lane & 3;
    const int qb = gridDim.x - 1 - blockIdx.x;    // longest CTAs first
    const int h = blockIdx.y, b = blockIdx.z;
    const int q0 = qb * 128;
    const int headoff = h * DK;
    const long rowbase = (long)(b * SEQ + q0 + warp * 16);
    const long vtbase  = (long)((b * NH + h) * DK) * SEQ;
    const float NEG_INF = __int_as_float(0xff800000);

    const int f_row = ((lane >> 4) << 3) + (lane & 7);
    const int f_hk  = ((lane >> 3) & 1) * 4;

    const int jmax = 2 * (qb + 1);

    auto prefetch = [&](int jb, int stg) {
        const int ch = tid & 7;
#pragma unroll
        for (int u = 0; u < 8; u++) {
            int arr = u >> 1;
            int r2  = ((u & 1) << 5) + (tid >> 3);
            const uint16_t* src;
            long koff = (long)(b * SEQ + jb * 64 + r2) * DM + headoff + ch * 8;
            long voff = vtbase + (long)r2 * SEQ + jb * 64 + ch * 8;
            if      (arr == 0) src = g_kh  + koff;
            else if (arr == 1) src = g_kl  + koff;
            else if (arr == 2) src = g_vth + voff;
            else               src = g_vtl + voff;
            uint32_t dst = smb + (uint32_t)(stg * STAGE_U32 + arr * ARR_U32 + r2 * VS) * 4 + ch * 16;
            CP16(dst, src);
        }
        CP_COMMIT();
    };

    prefetch(0, 0);   // overlap with Q fragment LDGs below

    // ---- Q fragments (already scaled + split) ----
    uint32_t qh[4][4], ql[4][4];
#pragma unroll
    for (int ks = 0; ks < 4; ks++) {
#pragma unroll
        for (int idx = 0; idx < 4; idx++) {
            int rr = (idx & 1) ? g + 8 : g;
            int d0 = ks * 16 + ((idx >> 1) ? 2 * t + 8 : 2 * t);
            long off = (rowbase + rr) * DM + headoff + d0;
            qh[ks][idx] = *(const uint32_t*)&g_qh[off];
            ql[ks][idx] = *(const uint32_t*)&g_ql[off];
        }
    }

    float m[2] = {NEG_INF, NEG_INF}, l[2] = {0.f, 0.f};
    float o[8][4];
#pragma unroll
    for (int dt = 0; dt < 8; dt++)
#pragma unroll
        for (int r = 0; r < 4; r++) o[dt][r] = 0.f;

    for (int jb = 0; jb < jmax; jb++) {
        const int stg = jb & 1;
        CP_WAIT0();
        __syncthreads();
        if (jb + 1 < jmax) prefetch(jb + 1, stg ^ 1);

        const uint32_t sK  = smb + (uint32_t)(stg * STAGE_U32) * 4;
        const uint32_t sKl = sK + ARR_U32 * 4;
        const uint32_t sVh = sK + 2 * ARR_U32 * 4;
        const uint32_t sVl = sK + 3 * ARR_U32 * 4;

        // ---- S = Q K^T (pair-interleaved: same-acc distance 4) ----
        float s[8][4];
#pragma unroll
        for (int nt = 0; nt < 8; nt++)
#pragma unroll
            for (int r = 0; r < 4; r++) s[nt][r] = 0.f;
#pragma unroll
        for (int ks = 0; ks < 4; ks++) {
#pragma unroll
            for (int pp = 0; pp < 2; pp++) {
                uint32_t off0 = (uint32_t)(((2*pp)   * 16 + f_row) * VS + ks * 8 + f_hk) * 4;
                uint32_t off1 = (uint32_t)(((2*pp+1) * 16 + f_row) * VS + ks * 8 + f_hk) * 4;
                uint32_t kh0[4], kl0[4], kh1[4], kl1[4];
                ldsm4(kh0, sK  + off0);
                ldsm4(kl0, sKl + off0);
                ldsm4(kh1, sK  + off1);
                ldsm4(kl1, sKl + off1);
                float* s0 = s[4*pp]; float* s1 = s[4*pp+1];
                float* s2 = s[4*pp+2]; float* s3 = s[4*pp+3];
                mma16816(s0, qh[ks], kh0); mma16816(s1, qh[ks], kh0 + 2);
                mma16816(s2, qh[ks], kh1); mma16816(s3, qh[ks], kh1 + 2);
                mma16816(s0, ql[ks], kh0); mma16816(s1, ql[ks], kh0 + 2);
                mma16816(s2, ql[ks], kh1); mma16816(s3, ql[ks], kh1 + 2);
                mma16816(s0, qh[ks], kl0); mma16816(s1, qh[ks], kl0 + 2);
                mma16816(s2, qh[ks], kl1); mma16816(s3, qh[ks], kl1 + 2);
            }
        }

        // ---- causal mask ----
        if (jb >= 2 * qb) {
#pragma unroll
            for (int nt = 0; nt < 8; nt++)
#pragma unroll
                for (int r = 0; r < 4; r++) {
                    int key = jb * 64 + nt * 8 + 2 * t + (r & 1);
                    int qr  = q0 + warp * 16 + g + ((r >> 1) ? 8 : 0);
                    if (key > qr) s[nt][r] = NEG_INF;
                }
        }

        // ---- online softmax ----
        float mx0 = NEG_INF, mx1 = NEG_INF;
#pragma unroll
        for (int nt = 0; nt < 8; nt++) {
            mx0 = fmaxf(mx0, fmaxf(s[nt][0], s[nt][1]));
            mx1 = fmaxf(mx1, fmaxf(s[nt][2], s[nt][3]));
        }
        mx0 = fmaxf(mx0, __shfl_xor_sync(0xffffffffu, mx0, 1));
        mx0 = fmaxf(mx0, __shfl_xor_sync(0xffffffffu, mx0, 2));
        mx1 = fmaxf(mx1, __shfl_xor_sync(0xffffffffu, mx1, 1));
        mx1 = fmaxf(mx1, __shfl_xor_sync(0xffffffffu, mx1, 2));
        float mn0 = fmaxf(m[0], mx0), mn1 = fmaxf(m[1], mx1);
        float al0 = __expf(m[0] - mn0), al1 = __expf(m[1] - mn1);
        m[0] = mn0; m[1] = mn1;
        float ps0 = 0.f, ps1 = 0.f;
#pragma unroll
        for (int nt = 0; nt < 8; nt++) {
            s[nt][0] = __expf(s[nt][0] - mn0); ps0 += s[nt][0];
            s[nt][1] = __expf(s[nt][1] - mn0); ps0 += s[nt][1];
            s[nt][2] = __expf(s[nt][2] - mn1); ps1 += s[nt][2];
            s[nt][3] = __expf(s[nt][3] - mn1); ps1 += s[nt][3];
        }
        ps0 += __shfl_xor_sync(0xffffffffu, ps0, 1);
        ps0 += __shfl_xor_sync(0xffffffffu, ps0, 2);
        ps1 += __shfl_xor_sync(0xffffffffu, ps1, 1);
        ps1 += __shfl_xor_sync(0xffffffffu, ps1, 2);
        l[0] = l[0] * al0 + ps0;
        l[1] = l[1] * al1 + ps1;
#pragma unroll
        for (int dt = 0; dt < 8; dt++) {
            o[dt][0] *= al0; o[dt][1] *= al0;
            o[dt][2] *= al1; o[dt][3] *= al1;
        }

        // ---- O += P V (pair-interleaved) ----
#pragma unroll
        for (int kt = 0; kt < 4; kt++) {
            uint32_t ph[4], pl[4];
            ph[0] = bfpack(s[2*kt][0],   s[2*kt][1]);
            ph[1] = bfpack(s[2*kt][2],   s[2*kt][3]);
            ph[2] = bfpack(s[2*kt+1][0], s[2*kt+1][1]);
            ph[3] = bfpack(s[2*kt+1][2], s[2*kt+1][3]);
            pl[0] = bfpack(s[2*kt][0]   - lo_of(ph[0]), s[2*kt][1]   - hi_of(ph[0]));
            pl[1] = bfpack(s[2*kt][2]   - lo_of(ph[1]), s[2*kt][3]   - hi_of(ph[1]));
            pl[2] = bfpack(s[2*kt+1][0] - lo_of(ph[2]), s[2*kt+1][1] - hi_of(ph[2]));
            pl[3] = bfpack(s[2*kt+1][2] - lo_of(ph[3]), s[2*kt+1][3] - hi_of(ph[3]));
#pragma unroll
            for (int pp = 0; pp < 2; pp++) {
                uint32_t off0 = (uint32_t)(((2*pp)   * 16 + f_row) * VS + kt * 8 + f_hk) * 4;
                uint32_t off1 = (uint32_t)(((2*pp+1) * 16 + f_row) * VS + kt * 8 + f_hk) * 4;
                uint32_t vh0[4], vl0[4], vh1[4], vl1[4];
                ldsm4(vh0, sVh + off0);
                ldsm4(vl0, sVl + off0);
                ldsm4(vh1, sVh + off1);
                ldsm4(vl1, sVl + off1);
                float* o0 = o[4*pp]; float* o1 = o[4*pp+1];
                float* o2 = o[4*pp+2]; float* o3 = o[4*pp+3];
                mma16816(o0, ph, vh0); mma16816(o1, ph, vh0 + 2);
                mma16816(o2, ph, vh1); mma16816(o3, ph, vh1 + 2);
                mma16816(o0, pl, vh0); mma16816(o1, pl, vh0 + 2);
                mma16816(o2, pl, vh1); mma16816(o3, pl, vh1 + 2);
                mma16816(o0, ph, vl0); mma16816(o1, ph, vl0 + 2);
                mma16816(o2, ph, vl1); mma16816(o3, ph, vl1 + 2);
            }
        }
    }

    // ---- epilogue: write bf16 hi/lo for the output projection ----
    float inv0 = 1.f / l[0], inv1 = 1.f / l[1];
#pragma unroll
    for (int dt = 0; dt < 8; dt++) {
        int col = headoff + dt * 8 + 2 * t;
        float a0 = o[dt][0] * inv0, a1 = o[dt][1] * inv0;
        float a2 = o[dt][2] * inv1, a3 = o[dt][3] * inv1;
        uint32_t h0 = bfpack(a0, a1), h1 = bfpack(a2, a3);
        *(uint32_t*)&g_ah[(rowbase + g) * DM + col]     = h0;
        *(uint32_t*)&g_al[(rowbase + g) * DM + col]     = bfpack(a0 - lo_of(h0), a1 - hi_of(h0));
        *(uint32_t*)&g_ah[(rowbase + g + 8) * DM + col] = h1;
        *(uint32_t*)&g_al[(rowbase + g + 8) * DM + col] = bfpack(a2 - lo_of(h1), a3 - hi_of(h1));
    }
}

// ---------------------------------------------------------------------------
extern "C" void kernel_launch(void* const* d_in, const int* in_sizes, int n_in,
                              void* d_out, int out_size)
{
    const float* x  = (const float*)d_in[0];
    const float* wq = (const float*)d_in[1];
    const float* wk = (const float*)d_in[2];
    const float* wv = (const float*)d_in[3];
    const float* wo = (const float*)d_in[4];
    float* out = (float*)d_out;

    cudaFuncSetAttribute(flash_mma,   cudaFuncAttributeMaxDynamicSharedMemorySize, FL_SMEM);
    cudaFuncSetAttribute(gemm_qkv,    cudaFuncAttributeMaxDynamicSharedMemorySize, G_SMEM);
    cudaFuncSetAttribute(gemm_out_sk, cudaFuncAttributeMaxDynamicSharedMemorySize, G_SMEM);

    const long ntot = NX4 + 4L * NW4;
    conv_all<<<(int)((ntot + 255) / 256), 256>>>(x, wq, wk, wv, wo);

    gemm_qkv<<<dim3(DM / 128, MROWS / 128, 3), 256, G_SMEM>>>();
    flash_mma<<<dim3(SEQ / 128, NH, BATCH), 256, FL_SMEM>>>();
    gemm_out_sk<<<dim3(DM / 128, MROWS / 128, 2), 256, G_SMEM>>>();
    add_out<<<(NX4 + 255) / 256, 256>>>(out);
}

// round 15
// speedup vs baseline: 1.0615x; 1.0010x over previous
#include <cuda_runtime.h>
#include <cstdint>

#define BATCH 2
#define SEQ   2048
#define DM    768
#define NH    12
#define DK    64
#define MROWS (BATCH*SEQ)

// Scratch (allocation-free rule: __device__ globals)
__device__ uint16_t g_xh[MROWS*DM],  g_xl[MROWS*DM];
__device__ uint16_t g_qh[MROWS*DM],  g_ql[MROWS*DM];
__device__ uint16_t g_kh[MROWS*DM],  g_kl[MROWS*DM];
__device__ uint16_t g_vth[MROWS*DM], g_vtl[MROWS*DM];
__device__ uint16_t g_ah[MROWS*DM],  g_al[MROWS*DM];
__device__ uint16_t g_wqh[DM*DM], g_wql[DM*DM];
__device__ uint16_t g_wkh[DM*DM], g_wkl[DM*DM];
__device__ uint16_t g_wvh[DM*DM], g_wvl[DM*DM];
__device__ uint16_t g_woh[DM*DM], g_wol[DM*DM];
__device__ float g_p0[MROWS*DM], g_p1[MROWS*DM];   // split-K partials

// ============================================================================
// helpers
// ============================================================================
__device__ __forceinline__ uint32_t smem_u32(const void* p) {
    uint32_t a;
    asm("{ .reg .u64 t; cvta.to.shared.u64 t, %1; cvt.u32.u64 %0, t; }" : "=r"(a) : "l"(p));
    return a;
}
__device__ __forceinline__ uint32_t bfpack(float x, float y) {
    uint32_t r;
    asm("cvt.rn.bf16x2.f32 %0, %1, %2;" : "=r"(r) : "f"(y), "f"(x));
    return r;
}
__device__ __forceinline__ float lo_of(uint32_t p)  { return __uint_as_float(p << 16); }
__device__ __forceinline__ float hi_of(uint32_t p)  { return __uint_as_float(p & 0xffff0000u); }
__device__ __forceinline__ uint16_t bf1(float x) {
    uint16_t u; asm("cvt.rn.bf16.f32 %0, %1;" : "=h"(u) : "f"(x)); return u;
}
__device__ __forceinline__ float bf1v(uint16_t u) { return __uint_as_float(((uint32_t)u) << 16); }

__device__ __forceinline__ void mma16816(float* c, const uint32_t* a, const uint32_t* b) {
    asm volatile(
        "mma.sync.aligned.m16n8k16.row.col.f32.bf16.bf16.f32 "
        "{%0,%1,%2,%3}, {%4,%5,%6,%7}, {%8,%9}, {%0,%1,%2,%3};"
        : "+f"(c[0]), "+f"(c[1]), "+f"(c[2]), "+f"(c[3])
        : "r"(a[0]), "r"(a[1]), "r"(a[2]), "r"(a[3]), "r"(b[0]), "r"(b[1]));
}
__device__ __forceinline__ void ldsm4(uint32_t* r, uint32_t addr) {
    asm volatile("ldmatrix.sync.aligned.m8n8.x4.shared.b16 {%0,%1,%2,%3}, [%4];"
        : "=r"(r[0]), "=r"(r[1]), "=r"(r[2]), "=r"(r[3]) : "r"(addr));
}
#define CP16(dst, src) asm volatile("cp.async.ca.shared.global [%0], [%1], 16;" :: "r"(dst), "l"(src))
#define CP_COMMIT()    asm volatile("cp.async.commit_group;" ::: "memory")
#define CP_WAIT0()     asm volatile("cp.async.wait_group 0;" ::: "memory")

// ============================================================================
// Single fused fp32 -> bf16 hi/lo split over x + 4 weights
// ============================================================================
#define NX4 (MROWS*DM/4)
#define NW4 (DM*DM/4)

__global__ __launch_bounds__(256) void conv_all(const float* __restrict__ x,
                                                const float* __restrict__ wq,
                                                const float* __restrict__ wk,
                                                const float* __restrict__ wv,
                                                const float* __restrict__ wo)
{
    long i = (long)blockIdx.x * blockDim.x + threadIdx.x;
    const float* src; uint16_t *dh, *dl; long j;
    if (i < NX4)                 { src = x;  dh = g_xh;  dl = g_xl;  j = i; }
    else if (i < NX4 + NW4)      { src = wq; dh = g_wqh; dl = g_wql; j = i - NX4; }
    else if (i < NX4 + 2*NW4)    { src = wk; dh = g_wkh; dl = g_wkl; j = i - NX4 - NW4; }
    else if (i < NX4 + 3*NW4)    { src = wv; dh = g_wvh; dl = g_wvl; j = i - NX4 - 2*NW4; }
    else if (i < NX4 + 4*NW4)    { src = wo; dh = g_woh; dl = g_wol; j = i - NX4 - 3*NW4; }
    else return;
    float4 v = ((const float4*)src)[j];
    uint32_t h0 = bfpack(v.x, v.y), h1 = bfpack(v.z, v.w);
    ((uint2*)dh)[j] = make_uint2(h0, h1);
    ((uint2*)dl)[j] = make_uint2(bfpack(v.x - lo_of(h0), v.y - hi_of(h0)),
                                 bfpack(v.z - lo_of(h1), v.w - hi_of(h1)));
}

// ============================================================================
// GEMM core (kc range for split-K): cp.async double-buffered, LDSM with
// ah-prefetch (mt+1 loaded during mt's MMAs), term-major mma (dist 4)
// ============================================================================
#define SROW 20
#define GST_U32 (128*SROW)
#define GSTAGE_U32 (4*GST_U32)
#define G_SMEM (2*GSTAGE_U32*4)        // 81920 B

__device__ __forceinline__ void gemm_core_bf(const uint16_t* __restrict__ Agh,
                                             const uint16_t* __restrict__ Agl,
                                             const uint16_t* __restrict__ Bgh,
                                             const uint16_t* __restrict__ Bgl,
                                             uint32_t smb, int m0, int n0,
                                             int kc0, int kc1,
                                             int tid, float c[4][4][4])
{
    const int warp = tid >> 5, lane = tid & 31;
    const int wm = warp >> 2, wn = warp & 3;
    const int a_row = lane & 15,                  a_hk = (lane >> 4) * 4;
    const int b_row = ((lane >> 4) << 3) + (lane & 7), b_hk = ((lane >> 3) & 1) * 4;

    auto pre = [&](int kc, int stg) {
#pragma unroll
        for (int u = 0; u < 8; u++) {
            int idx = tid + u * 256;
            int arr = idx >> 9, row = (idx >> 2) & 127, ch = idx & 3;
            const uint16_t* src;
            if      (arr == 0) src = Agh + (long)(m0 + row) * DM + kc * 32 + ch * 8;
            else if (arr == 1) src = Agl + (long)(m0 + row) * DM + kc * 32 + ch * 8;
            else if (arr == 2) src = Bgh + (long)(n0 + row) * DM + kc * 32 + ch * 8;
            else               src = Bgl + (long)(n0 + row) * DM + kc * 32 + ch * 8;
            uint32_t dst = smb + (uint32_t)((stg * 4 + arr) * GST_U32 + row * SROW + ch * 4) * 4;
            CP16(dst, src);
        }
        CP_COMMIT();
    };

    pre(kc0, 0);

    for (int kc = kc0; kc < kc1; kc++) {
        const int stg = (kc - kc0) & 1;
        CP_WAIT0();
        __syncthreads();
        if (kc + 1 < kc1) pre(kc + 1, stg ^ 1);

        const uint32_t sAh = smb + (uint32_t)(stg * GSTAGE_U32) * 4;
        const uint32_t sAl = sAh + GST_U32 * 4;
        const uint32_t sBh = sAh + 2 * GST_U32 * 4;
        const uint32_t sBl = sAh + 3 * GST_U32 * 4;

#pragma unroll
        for (int ks = 0; ks < 2; ks++) {
            uint32_t bh[4][2], bl[4][2];
#pragma unroll
            for (int p = 0; p < 2; p++) {
                uint32_t off = (uint32_t)((wn * 32 + p * 16 + b_row) * SROW + ks * 8 + b_hk) * 4;
                uint32_t rr[4];
                ldsm4(rr, sBh + off);
                bh[2*p][0] = rr[0]; bh[2*p][1] = rr[1];
                bh[2*p+1][0] = rr[2]; bh[2*p+1][1] = rr[3];
                ldsm4(rr, sBl + off);
                bl[2*p][0] = rr[0]; bl[2*p][1] = rr[1];
                bl[2*p+1][0] = rr[2]; bl[2*p+1][1] = rr[3];
            }
            uint32_t ahf[2][4], al[4];
            ldsm4(ahf[0], sAh + (uint32_t)((wm * 64 + a_row) * SROW + ks * 8 + a_hk) * 4);
#pragma unroll
            for (int mt = 0; mt < 4; mt++) {
                uint32_t off = (uint32_t)((wm * 64 + mt * 16 + a_row) * SROW + ks * 8 + a_hk) * 4;
                ldsm4(al, sAl + off);
                if (mt < 3) {
                    uint32_t offn = (uint32_t)((wm * 64 + (mt + 1) * 16 + a_row) * SROW + ks * 8 + a_hk) * 4;
                    ldsm4(ahf[(mt + 1) & 1], sAh + offn);
                }
                const uint32_t* ac = ahf[mt & 1];
#pragma unroll
                for (int nt = 0; nt < 4; nt++) mma16816(c[mt][nt], ac, bh[nt]);
#pragma unroll
                for (int nt = 0; nt < 4; nt++) mma16816(c[mt][nt], al, bh[nt]);
#pragma unroll
                for (int nt = 0; nt < 4; nt++) mma16816(c[mt][nt], ac, bl[nt]);
            }
        }
    }
}

// ============================================================================
// Fused QKV projection
// ============================================================================
__global__ __launch_bounds__(256, 2) void gemm_qkv()
{
    extern __shared__ __align__(16) uint32_t dsm[];
    const uint32_t smb = smem_u32(dsm);

    const int tid  = threadIdx.x;
    const int warp = tid >> 5, lane = tid & 31;
    const int g = lane >> 2, t = lane & 3;
    const int wm = warp >> 2, wn = warp & 3;
    const int m0 = blockIdx.y * 128, n0 = blockIdx.x * 128;
    const int z = blockIdx.z;
    const uint16_t* Bgh = (z == 0) ? g_wqh : ((z == 1) ? g_wkh : g_wvh);
    const uint16_t* Bgl = (z == 0) ? g_wql : ((z == 1) ? g_wkl : g_wvl);

    float c[4][4][4];
#pragma unroll
    for (int i = 0; i < 4; i++)
#pragma unroll
        for (int j = 0; j < 4; j++)
#pragma unroll
            for (int r = 0; r < 4; r++) c[i][j][r] = 0.f;

    gemm_core_bf(g_xh, g_xl, Bgh, Bgl, smb, m0, n0, 0, DM/32, tid, c);

    if (z < 2) {
        uint16_t* Hh = (z == 0) ? g_qh : g_kh;
        uint16_t* Hl = (z == 0) ? g_ql : g_kl;
        const float sc = (z == 0) ? 0.125f : 1.0f;
#pragma unroll
        for (int mt = 0; mt < 4; mt++) {
#pragma unroll
            for (int nt = 0; nt < 4; nt++) {
                int row = m0 + wm * 64 + mt * 16 + g;
                int col = n0 + wn * 32 + nt * 8 + 2 * t;
                float x0 = c[mt][nt][0] * sc, x1 = c[mt][nt][1] * sc;
                float x2 = c[mt][nt][2] * sc, x3 = c[mt][nt][3] * sc;
                uint32_t h0 = bfpack(x0, x1), h1 = bfpack(x2, x3);
                *(uint32_t*)&Hh[(long)row * DM + col]       = h0;
                *(uint32_t*)&Hl[(long)row * DM + col]       = bfpack(x0 - lo_of(h0), x1 - hi_of(h0));
                *(uint32_t*)&Hh[(long)(row + 8) * DM + col] = h1;
                *(uint32_t*)&Hl[(long)(row + 8) * DM + col] = bfpack(x2 - lo_of(h1), x3 - hi_of(h1));
            }
        }
    } else {
        uint16_t* st = (uint16_t*)dsm;
        const int b = m0 / SEQ, s0 = m0 % SEQ;
#pragma unroll
        for (int pass = 0; pass < 2; pass++) {
            __syncthreads();
#pragma unroll
            for (int mt = 0; mt < 4; mt++)
#pragma unroll
                for (int nt = 0; nt < 4; nt++)
#pragma unroll
                    for (int r = 0; r < 4; r++) {
                        float cv = c[mt][nt][r];
                        uint16_t hv = bf1(cv);
                        uint16_t val = pass ? bf1(cv - bf1v(hv)) : hv;
                        int rowl = wm * 64 + mt * 16 + g + ((r >> 1) ? 8 : 0);
                        int coll = wn * 32 + nt * 8 + 2 * t + (r & 1);
                        st[coll * 136 + rowl] = val;
                    }
            __syncthreads();
            uint16_t* dstb = pass ? g_vtl : g_vth;
#pragma unroll
            for (int u = 0; u < 8; u++) {
                int idx = tid + u * 256;
                int dl128 = idx >> 4, ch = idx & 15;
                uint4 v = *(const uint4*)&st[dl128 * 136 + ch * 8];
                int colg = n0 + dl128;
                int hh = colg >> 6, dl = colg & 63;
                *(uint4*)&dstb[((long)((b * NH + hh) * DK + dl)) * SEQ + s0 + ch * 8] = v;
            }
        }
    }
}

// ============================================================================
// Output projection: split-K2 into partials, then add
// ============================================================================
__global__ __launch_bounds__(256, 2) void gemm_out_sk()
{
    extern __shared__ __align__(16) uint32_t dsm[];
    const uint32_t smb = smem_u32(dsm);

    const int tid  = threadIdx.x;
    const int warp = tid >> 5, lane = tid & 31;
    const int g = lane >> 2, t = lane & 3;
    const int wm = warp >> 2, wn = warp & 3;
    const int m0 = blockIdx.y * 128, n0 = blockIdx.x * 128;
    const int z = blockIdx.z;
    float* P = z ? g_p1 : g_p0;

    float c[4][4][4];
#pragma unroll
    for (int i = 0; i < 4; i++)
#pragma unroll
        for (int j = 0; j < 4; j++)
#pragma unroll
            for (int r = 0; r < 4; r++) c[i][j][r] = 0.f;

    gemm_core_bf(g_ah, g_al, g_woh, g_wol, smb, m0, n0, z * 12, (z + 1) * 12, tid, c);

#pragma unroll
    for (int mt = 0; mt < 4; mt++) {
#pragma unroll
        for (int nt = 0; nt < 4; nt++) {
            int row = m0 + wm * 64 + mt * 16 + g;
            int col = n0 + wn * 32 + nt * 8 + t * 2;
            *(float2*)&P[(long)row * DM + col]       = make_float2(c[mt][nt][0], c[mt][nt][1]);
            *(float2*)&P[(long)(row + 8) * DM + col] = make_float2(c[mt][nt][2], c[mt][nt][3]);
        }
    }
}

__global__ __launch_bounds__(256) void add_out(float* __restrict__ out)
{
    int i = blockIdx.x * blockDim.x + threadIdx.x;
    if (i < NX4) {
        float4 a = ((const float4*)g_p0)[i];
        float4 b = ((const float4*)g_p1)[i];
        ((float4*)out)[i] = make_float4(a.x + b.x, a.y + b.y, a.z + b.z, a.w + b.w);
    }
}

// ============================================================================
// Flash attention: Q fragments in registers, cp.async double-buffered K/V,
// batched LDSM (8 up front) + term-major MMAs (same-acc dist 8), longest-qb
// first. BQ=128, BK=64. grid = (SEQ/128, NH, BATCH).
// ============================================================================
#define VS 36
#define ARR_U32 (64*VS)
#define STAGE_U32 (4*ARR_U32)
#define FL_SMEM (2*STAGE_U32*4)         // 73728 B

__global__ __launch_bounds__(256) void flash_mma()
{
    extern __shared__ __align__(16) uint32_t fsm[];
    const uint32_t smb = smem_u32(fsm);

    const int tid  = threadIdx.x;
    const int warp = tid >> 5, lane = tid & 31;
    const int g = lane >> 2, t = lane & 3;
    const int qb = gridDim.x - 1 - blockIdx.x;    // longest CTAs first
    const int h = blockIdx.y, b = blockIdx.z;
    const int q0 = qb * 128;
    const int headoff = h * DK;
    const long rowbase = (long)(b * SEQ + q0 + warp * 16);
    const long vtbase  = (long)((b * NH + h) * DK) * SEQ;
    const float NEG_INF = __int_as_float(0xff800000);

    const int f_row = ((lane >> 4) << 3) + (lane & 7);
    const int f_hk  = ((lane >> 3) & 1) * 4;

    const int jmax = 2 * (qb + 1);

    auto prefetch = [&](int jb, int stg) {
        const int ch = tid & 7;
#pragma unroll
        for (int u = 0; u < 8; u++) {
            int arr = u >> 1;
            int r2  = ((u & 1) << 5) + (tid >> 3);
            const uint16_t* src;
            long koff = (long)(b * SEQ + jb * 64 + r2) * DM + headoff + ch * 8;
            long voff = vtbase + (long)r2 * SEQ + jb * 64 + ch * 8;
            if      (arr == 0) src = g_kh  + koff;
            else if (arr == 1) src = g_kl  + koff;
            else if (arr == 2) src = g_vth + voff;
            else               src = g_vtl + voff;
            uint32_t dst = smb + (uint32_t)(stg * STAGE_U32 + arr * ARR_U32 + r2 * VS) * 4 + ch * 16;
            CP16(dst, src);
        }
        CP_COMMIT();
    };

    prefetch(0, 0);   // overlap with Q fragment LDGs below

    // ---- Q fragments (already scaled + split) ----
    uint32_t qh[4][4], ql[4][4];
#pragma unroll
    for (int ks = 0; ks < 4; ks++) {
#pragma unroll
        for (int idx = 0; idx < 4; idx++) {
            int rr = (idx & 1) ? g + 8 : g;
            int d0 = ks * 16 + ((idx >> 1) ? 2 * t + 8 : 2 * t);
            long off = (rowbase + rr) * DM + headoff + d0;
            qh[ks][idx] = *(const uint32_t*)&g_qh[off];
            ql[ks][idx] = *(const uint32_t*)&g_ql[off];
        }
    }

    float m[2] = {NEG_INF, NEG_INF}, l[2] = {0.f, 0.f};
    float o[8][4];
#pragma unroll
    for (int dt = 0; dt < 8; dt++)
#pragma unroll
        for (int r = 0; r < 4; r++) o[dt][r] = 0.f;

    for (int jb = 0; jb < jmax; jb++) {
        const int stg = jb & 1;
        CP_WAIT0();
        __syncthreads();
        if (jb + 1 < jmax) prefetch(jb + 1, stg ^ 1);

        const uint32_t sK  = smb + (uint32_t)(stg * STAGE_U32) * 4;
        const uint32_t sKl = sK + ARR_U32 * 4;
        const uint32_t sVh = sK + 2 * ARR_U32 * 4;
        const uint32_t sVl = sK + 3 * ARR_U32 * 4;

        // ---- S = Q K^T: 8 LDSM batched, then 24 MMAs term-major (dist 8) ----
        float s[8][4];
#pragma unroll
        for (int nt = 0; nt < 8; nt++)
#pragma unroll
            for (int r = 0; r < 4; r++) s[nt][r] = 0.f;
#pragma unroll
        for (int ks = 0; ks < 4; ks++) {
            uint32_t kh[4][4], kl[4][4];
#pragma unroll
            for (int p = 0; p < 4; p++) {
                uint32_t off = (uint32_t)((p * 16 + f_row) * VS + ks * 8 + f_hk) * 4;
                ldsm4(kh[p], sK  + off);
                ldsm4(kl[p], sKl + off);
            }
#pragma unroll
            for (int p = 0; p < 4; p++) {
                mma16816(s[2*p],   qh[ks], kh[p]);
                mma16816(s[2*p+1], qh[ks], kh[p] + 2);
            }
#pragma unroll
            for (int p = 0; p < 4; p++) {
                mma16816(s[2*p],   ql[ks], kh[p]);
                mma16816(s[2*p+1], ql[ks], kh[p] + 2);
            }
#pragma unroll
            for (int p = 0; p < 4; p++) {
                mma16816(s[2*p],   qh[ks], kl[p]);
                mma16816(s[2*p+1], qh[ks], kl[p] + 2);
            }
        }

        // ---- causal mask ----
        if (jb >= 2 * qb) {
#pragma unroll
            for (int nt = 0; nt < 8; nt++)
#pragma unroll
                for (int r = 0; r < 4; r++) {
                    int key = jb * 64 + nt * 8 + 2 * t + (r & 1);
                    int qr  = q0 + warp * 16 + g + ((r >> 1) ? 8 : 0);
                    if (key > qr) s[nt][r] = NEG_INF;
                }
        }

        // ---- online softmax ----
        float mx0 = NEG_INF, mx1 = NEG_INF;
#pragma unroll
        for (int nt = 0; nt < 8; nt++) {
            mx0 = fmaxf(mx0, fmaxf(s[nt][0], s[nt][1]));
            mx1 = fmaxf(mx1, fmaxf(s[nt][2], s[nt][3]));
        }
        mx0 = fmaxf(mx0, __shfl_xor_sync(0xffffffffu, mx0, 1));
        mx0 = fmaxf(mx0, __shfl_xor_sync(0xffffffffu, mx0, 2));
        mx1 = fmaxf(mx1, __shfl_xor_sync(0xffffffffu, mx1, 1));
        mx1 = fmaxf(mx1, __shfl_xor_sync(0xffffffffu, mx1, 2));
        float mn0 = fmaxf(m[0], mx0), mn1 = fmaxf(m[1], mx1);
        float al0 = __expf(m[0] - mn0), al1 = __expf(m[1] - mn1);
        m[0] = mn0; m[1] = mn1;
        float ps0 = 0.f, ps1 = 0.f;
#pragma unroll
        for (int nt = 0; nt < 8; nt++) {
            s[nt][0] = __expf(s[nt][0] - mn0); ps0 += s[nt][0];
            s[nt][1] = __expf(s[nt][1] - mn0); ps0 += s[nt][1];
            s[nt][2] = __expf(s[nt][2] - mn1); ps1 += s[nt][2];
            s[nt][3] = __expf(s[nt][3] - mn1); ps1 += s[nt][3];
        }
        ps0 += __shfl_xor_sync(0xffffffffu, ps0, 1);
        ps0 += __shfl_xor_sync(0xffffffffu, ps0, 2);
        ps1 += __shfl_xor_sync(0xffffffffu, ps1, 1);
        ps1 += __shfl_xor_sync(0xffffffffu, ps1, 2);
        l[0] = l[0] * al0 + ps0;
        l[1] = l[1] * al1 + ps1;
#pragma unroll
        for (int dt = 0; dt < 8; dt++) {
            o[dt][0] *= al0; o[dt][1] *= al0;
            o[dt][2] *= al1; o[dt][3] *= al1;
        }

        // ---- O += P V: 8 LDSM batched, 24 MMAs term-major (dist 8) ----
#pragma unroll
        for (int kt = 0; kt < 4; kt++) {
            uint32_t ph[4], pl[4];
            ph[0] = bfpack(s[2*kt][0],   s[2*kt][1]);
            ph[1] = bfpack(s[2*kt][2],   s[2*kt][3]);
            ph[2] = bfpack(s[2*kt+1][0], s[2*kt+1][1]);
            ph[3] = bfpack(s[2*kt+1][2], s[2*kt+1][3]);
            pl[0] = bfpack(s[2*kt][0]   - lo_of(ph[0]), s[2*kt][1]   - hi_of(ph[0]));
            pl[1] = bfpack(s[2*kt][2]   - lo_of(ph[1]), s[2*kt][3]   - hi_of(ph[1]));
            pl[2] = bfpack(s[2*kt+1][0] - lo_of(ph[2]), s[2*kt+1][1] - hi_of(ph[2]));
            pl[3] = bfpack(s[2*kt+1][2] - lo_of(ph[3]), s[2*kt+1][3] - hi_of(ph[3]));
            uint32_t vh[4][4], vl[4][4];
#pragma unroll
            for (int p = 0; p < 4; p++) {
                uint32_t off = (uint32_t)((p * 16 + f_row) * VS + kt * 8 + f_hk) * 4;
                ldsm4(vh[p], sVh + off);
                ldsm4(vl[p], sVl + off);
            }
#pragma unroll
            for (int p = 0; p < 4; p++) {
                mma16816(o[2*p],   ph, vh[p]);
                mma16816(o[2*p+1], ph, vh[p] + 2);
            }
#pragma unroll
            for (int p = 0; p < 4; p++) {
                mma16816(o[2*p],   pl, vh[p]);
                mma16816(o[2*p+1], pl, vh[p] + 2);
            }
#pragma unroll
            for (int p = 0; p < 4; p++) {
                mma16816(o[2*p],   ph, vl[p]);
                mma16816(o[2*p+1], ph, vl[p] + 2);
            }
        }
    }

    // ---- epilogue: write bf16 hi/lo for the output projection ----
    float inv0 = 1.f / l[0], inv1 = 1.f / l[1];
#pragma unroll
    for (int dt = 0; dt < 8; dt++) {
        int col = headoff + dt * 8 + 2 * t;
        float a0 = o[dt][0] * inv0, a1 = o[dt][1] * inv0;
        float a2 = o[dt][2] * inv1, a3 = o[dt][3] * inv1;
        uint32_t h0 = bfpack(a0, a1), h1 = bfpack(a2, a3);
        *(uint32_t*)&g_ah[(rowbase + g) * DM + col]     = h0;
        *(uint32_t*)&g_al[(rowbase + g) * DM + col]     = bfpack(a0 - lo_of(h0), a1 - hi_of(h0));
        *(uint32_t*)&g_ah[(rowbase + g + 8) * DM + col] = h1;
        *(uint32_t*)&g_al[(rowbase + g + 8) * DM + col] = bfpack(a2 - lo_of(h1), a3 - hi_of(h1));
    }
}

// ---------------------------------------------------------------------------
extern "C" void kernel_launch(void* const* d_in, const int* in_sizes, int n_in,
                              void* d_out, int out_size)
{
    const float* x  = (const float*)d_in[0];
    const float* wq = (const float*)d_in[1];
    const float* wk = (const float*)d_in[2];
    const float* wv = (const float*)d_in[3];
    const float* wo = (const float*)d_in[4];
    float* out = (float*)d_out;

    cudaFuncSetAttribute(flash_mma,   cudaFuncAttributeMaxDynamicSharedMemorySize, FL_SMEM);
    cudaFuncSetAttribute(gemm_qkv,    cudaFuncAttributeMaxDynamicSharedMemorySize, G_SMEM);
    cudaFuncSetAttribute(gemm_out_sk, cudaFuncAttributeMaxDynamicSharedMemorySize, G_SMEM);

    const long ntot = NX4 + 4L * NW4;
    conv_all<<<(int)((ntot + 255) / 256), 256>>>(x, wq, wk, wv, wo);

    gemm_qkv<<<dim3(DM / 128, MROWS / 128, 3), 256, G_SMEM>>>();
    flash_mma<<<dim3(SEQ / 128, NH, BATCH), 256, FL_SMEM>>>();
    gemm_out_sk<<<dim3(DM / 128, MROWS / 128, 2), 256, G_SMEM>>>();
    add_out<<<(NX4 + 255) / 256, 256>>>(out);
}

// round 16
// speedup vs baseline: 1.4113x; 1.3296x over previous
#include <cuda_runtime.h>
#include <cuda_fp16.h>
#include <cstdint>

#define BATCH 2
#define SEQ   2048
#define DM    768
#define NH    12
#define DK    64
#define MROWS (BATCH*SEQ)

// Scratch (allocation-free rule: __device__ globals)
// A-side operands are 22-bit (fp16 hi/lo pairs); B-side are 11-bit (single fp16).
__device__ uint16_t g_xh[MROWS*DM], g_xl[MROWS*DM];   // x split
__device__ uint16_t g_qh[MROWS*DM], g_ql[MROWS*DM];   // Q split (pre-scaled)
__device__ uint16_t g_k [MROWS*DM];                   // K single fp16 [token][d]
__device__ uint16_t g_vt[MROWS*DM];                   // V^T single fp16 [(b,h,dl)][token]
__device__ uint16_t g_ah[MROWS*DM], g_al[MROWS*DM];   // attention out split
__device__ uint16_t g_wq[DM*DM], g_wk[DM*DM], g_wv[DM*DM], g_wo[DM*DM];  // weights single
__device__ float g_p0[MROWS*DM], g_p1[MROWS*DM];      // split-K partials

// ============================================================================
// helpers
// ============================================================================
__device__ __forceinline__ uint32_t smem_u32(const void* p) {
    uint32_t a;
    asm("{ .reg .u64 t; cvta.to.shared.u64 t, %1; cvt.u32.u64 %0, t; }" : "=r"(a) : "l"(p));
    return a;
}
__device__ __forceinline__ uint32_t hpack(float x, float y) {
    __half2 h = __floats2half2_rn(x, y);       // x -> low, y -> high
    return *(uint32_t*)&h;
}
__device__ __forceinline__ float hlo(uint32_t p) { __half2 h = *(__half2*)&p; return __low2float(h); }
__device__ __forceinline__ float hhi(uint32_t p) { __half2 h = *(__half2*)&p; return __high2float(h); }
__device__ __forceinline__ uint16_t h1(float x) { __half h = __float2half_rn(x); return *(uint16_t*)&h; }
__device__ __forceinline__ float h1v(uint16_t u) { __half h = *(__half*)&u; return __half2float(h); }

__device__ __forceinline__ void mma16816(float* c, const uint32_t* a, const uint32_t* b) {
    asm volatile(
        "mma.sync.aligned.m16n8k16.row.col.f32.f16.f16.f32 "
        "{%0,%1,%2,%3}, {%4,%5,%6,%7}, {%8,%9}, {%0,%1,%2,%3};"
        : "+f"(c[0]), "+f"(c[1]), "+f"(c[2]), "+f"(c[3])
        : "r"(a[0]), "r"(a[1]), "r"(a[2]), "r"(a[3]), "r"(b[0]), "r"(b[1]));
}
__device__ __forceinline__ void ldsm4(uint32_t* r, uint32_t addr) {
    asm volatile("ldmatrix.sync.aligned.m8n8.x4.shared.b16 {%0,%1,%2,%3}, [%4];"
        : "=r"(r[0]), "=r"(r[1]), "=r"(r[2]), "=r"(r[3]) : "r"(addr));
}
#define CP16(dst, src) asm volatile("cp.async.ca.shared.global [%0], [%1], 16;" :: "r"(dst), "l"(src))
#define CP_COMMIT()    asm volatile("cp.async.commit_group;" ::: "memory")
#define CP_WAIT0()     asm volatile("cp.async.wait_group 0;" ::: "memory")

// ============================================================================
// Fused fp32 -> fp16 conversion: x split hi/lo, weights single fp16
// ============================================================================
#define NX4 (MROWS*DM/4)
#define NW4 (DM*DM/4)

__global__ __launch_bounds__(256) void conv_all(const float* __restrict__ x,
                                                const float* __restrict__ wq,
                                                const float* __restrict__ wk,
                                                const float* __restrict__ wv,
                                                const float* __restrict__ wo)
{
    long i = (long)blockIdx.x * blockDim.x + threadIdx.x;
    if (i < NX4) {
        float4 v = ((const float4*)x)[i];
        uint32_t h0 = hpack(v.x, v.y), h1p = hpack(v.z, v.w);
        ((uint2*)g_xh)[i] = make_uint2(h0, h1p);
        ((uint2*)g_xl)[i] = make_uint2(hpack(v.x - hlo(h0), v.y - hhi(h0)),
                                       hpack(v.z - hlo(h1p), v.w - hhi(h1p)));
        return;
    }
    long r = i - NX4;
    const float* src; uint16_t* dh; long j;
    if      (r < NW4)     { src = wq; dh = g_wq; j = r; }
    else if (r < 2*NW4)   { src = wk; dh = g_wk; j = r - NW4; }
    else if (r < 3*NW4)   { src = wv; dh = g_wv; j = r - 2*NW4; }
    else if (r < 4*NW4)   { src = wo; dh = g_wo; j = r - 3*NW4; }
    else return;
    float4 v = ((const float4*)src)[j];
    ((uint2*)dh)[j] = make_uint2(hpack(v.x, v.y), hpack(v.z, v.w));
}

// ============================================================================
// GEMM core: A split (Agh/Agl, 22-bit), B single (Bg, 11-bit).
// cp.async double-buffered, LDSM, 2 MMAs per fragment set.
// ============================================================================
#define SROW 20
#define GST_U32 (128*SROW)
#define GSTAGE_U32 (3*GST_U32)
#define G_SMEM (2*GSTAGE_U32*4)        // 61440 B

__device__ __forceinline__ void gemm_core_2t(const uint16_t* __restrict__ Agh,
                                             const uint16_t* __restrict__ Agl,
                                             const uint16_t* __restrict__ Bg,
                                             uint32_t smb, int m0, int n0,
                                             int kc0, int kc1,
                                             int tid, float c[4][4][4])
{
    const int warp = tid >> 5, lane = tid & 31;
    const int wm = warp >> 2, wn = warp & 3;
    const int a_row = lane & 15,                  a_hk = (lane >> 4) * 4;
    const int b_row = ((lane >> 4) << 3) + (lane & 7), b_hk = ((lane >> 3) & 1) * 4;

    auto pre = [&](int kc, int stg) {
#pragma unroll
        for (int u = 0; u < 6; u++) {
            int idx = tid + u * 256;              // 1536 chunks: 3 arrays x 128 rows x 4
            int arr = idx >> 9, row = (idx >> 2) & 127, ch = idx & 3;
            const uint16_t* src;
            if      (arr == 0) src = Agh + (long)(m0 + row) * DM + kc * 32 + ch * 8;
            else if (arr == 1) src = Agl + (long)(m0 + row) * DM + kc * 32 + ch * 8;
            else               src = Bg  + (long)(n0 + row) * DM + kc * 32 + ch * 8;
            uint32_t dst = smb + (uint32_t)((stg * 3 + arr) * GST_U32 + row * SROW + ch * 4) * 4;
            CP16(dst, src);
        }
        CP_COMMIT();
    };

    pre(kc0, 0);

    for (int kc = kc0; kc < kc1; kc++) {
        const int stg = (kc - kc0) & 1;
        CP_WAIT0();
        __syncthreads();
        if (kc + 1 < kc1) pre(kc + 1, stg ^ 1);

        const uint32_t sAh = smb + (uint32_t)(stg * GSTAGE_U32) * 4;
        const uint32_t sAl = sAh + GST_U32 * 4;
        const uint32_t sB  = sAh + 2 * GST_U32 * 4;

#pragma unroll
        for (int ks = 0; ks < 2; ks++) {
            uint32_t bh[4][2];
#pragma unroll
            for (int p = 0; p < 2; p++) {
                uint32_t off = (uint32_t)((wn * 32 + p * 16 + b_row) * SROW + ks * 8 + b_hk) * 4;
                uint32_t rr[4];
                ldsm4(rr, sB + off);
                bh[2*p][0] = rr[0]; bh[2*p][1] = rr[1];
                bh[2*p+1][0] = rr[2]; bh[2*p+1][1] = rr[3];
            }
#pragma unroll
            for (int mt = 0; mt < 4; mt++) {
                uint32_t off = (uint32_t)((wm * 64 + mt * 16 + a_row) * SROW + ks * 8 + a_hk) * 4;
                uint32_t ah[4], al[4];
                ldsm4(ah, sAh + off);
                ldsm4(al, sAl + off);
#pragma unroll
                for (int nt = 0; nt < 4; nt++) mma16816(c[mt][nt], ah, bh[nt]);
#pragma unroll
                for (int nt = 0; nt < 4; nt++) mma16816(c[mt][nt], al, bh[nt]);
            }
        }
    }
}

// ============================================================================
// Fused QKV projection (z picks weight + epilogue format)
// ============================================================================
__global__ __launch_bounds__(256, 2) void gemm_qkv()
{
    extern __shared__ __align__(16) uint32_t dsm[];
    const uint32_t smb = smem_u32(dsm);

    const int tid  = threadIdx.x;
    const int warp = tid >> 5, lane = tid & 31;
    const int g = lane >> 2, t = lane & 3;
    const int wm = warp >> 2, wn = warp & 3;
    const int m0 = blockIdx.y * 128, n0 = blockIdx.x * 128;
    const int z = blockIdx.z;
    const uint16_t* Bg = (z == 0) ? g_wq : ((z == 1) ? g_wk : g_wv);

    float c[4][4][4];
#pragma unroll
    for (int i = 0; i < 4; i++)
#pragma unroll
        for (int j = 0; j < 4; j++)
#pragma unroll
            for (int r = 0; r < 4; r++) c[i][j][r] = 0.f;

    gemm_core_2t(g_xh, g_xl, Bg, smb, m0, n0, 0, DM/32, tid, c);

    if (z == 0) {
        // Q: scaled fp16 split
#pragma unroll
        for (int mt = 0; mt < 4; mt++) {
#pragma unroll
            for (int nt = 0; nt < 4; nt++) {
                int row = m0 + wm * 64 + mt * 16 + g;
                int col = n0 + wn * 32 + nt * 8 + 2 * t;
                float x0 = c[mt][nt][0] * 0.125f, x1 = c[mt][nt][1] * 0.125f;
                float x2 = c[mt][nt][2] * 0.125f, x3 = c[mt][nt][3] * 0.125f;
                uint32_t h0 = hpack(x0, x1), h1p = hpack(x2, x3);
                *(uint32_t*)&g_qh[(long)row * DM + col]       = h0;
                *(uint32_t*)&g_ql[(long)row * DM + col]       = hpack(x0 - hlo(h0), x1 - hhi(h0));
                *(uint32_t*)&g_qh[(long)(row + 8) * DM + col] = h1p;
                *(uint32_t*)&g_ql[(long)(row + 8) * DM + col] = hpack(x2 - hlo(h1p), x3 - hhi(h1p));
            }
        }
    } else if (z == 1) {
        // K: single fp16
#pragma unroll
        for (int mt = 0; mt < 4; mt++) {
#pragma unroll
            for (int nt = 0; nt < 4; nt++) {
                int row = m0 + wm * 64 + mt * 16 + g;
                int col = n0 + wn * 32 + nt * 8 + 2 * t;
                *(uint32_t*)&g_k[(long)row * DM + col]       = hpack(c[mt][nt][0], c[mt][nt][1]);
                *(uint32_t*)&g_k[(long)(row + 8) * DM + col] = hpack(c[mt][nt][2], c[mt][nt][3]);
            }
        }
    } else {
        // V: transpose 128x128 tile via smem, single fp16 [(b,h,dl)][token]
        uint16_t* st = (uint16_t*)dsm;      // 128 x 136 u16 = 34816 B (< 61440)
        const int b = m0 / SEQ, s0 = m0 % SEQ;
        __syncthreads();
#pragma unroll
        for (int mt = 0; mt < 4; mt++)
#pragma unroll
            for (int nt = 0; nt < 4; nt++)
#pragma unroll
                for (int r = 0; r < 4; r++) {
                    int rowl = wm * 64 + mt * 16 + g + ((r >> 1) ? 8 : 0);
                    int coll = wn * 32 + nt * 8 + 2 * t + (r & 1);
                    st[coll * 136 + rowl] = h1(c[mt][nt][r]);
                }
        __syncthreads();
#pragma unroll
        for (int u = 0; u < 8; u++) {
            int idx = tid + u * 256;
            int dl128 = idx >> 4, ch = idx & 15;
            uint4 v = *(const uint4*)&st[dl128 * 136 + ch * 8];
            int colg = n0 + dl128;
            int hh = colg >> 6, dl = colg & 63;
            *(uint4*)&g_vt[((long)((b * NH + hh) * DK + dl)) * SEQ + s0 + ch * 8] = v;
        }
    }
}

// ============================================================================
// Output projection: split-K2 into partials, then add
// ============================================================================
__global__ __launch_bounds__(256, 2) void gemm_out_sk()
{
    extern __shared__ __align__(16) uint32_t dsm[];
    const uint32_t smb = smem_u32(dsm);

    const int tid  = threadIdx.x;
    const int warp = tid >> 5, lane = tid & 31;
    const int g = lane >> 2, t = lane & 3;
    const int wm = warp >> 2, wn = warp & 3;
    const int m0 = blockIdx.y * 128, n0 = blockIdx.x * 128;
    const int z = blockIdx.z;
    float* P = z ? g_p1 : g_p0;

    float c[4][4][4];
#pragma unroll
    for (int i = 0; i < 4; i++)
#pragma unroll
        for (int j = 0; j < 4; j++)
#pragma unroll
            for (int r = 0; r < 4; r++) c[i][j][r] = 0.f;

    gemm_core_2t(g_ah, g_al, g_wo, smb, m0, n0, z * 12, (z + 1) * 12, tid, c);

#pragma unroll
    for (int mt = 0; mt < 4; mt++) {
#pragma unroll
        for (int nt = 0; nt < 4; nt++) {
            int row = m0 + wm * 64 + mt * 16 + g;
            int col = n0 + wn * 32 + nt * 8 + t * 2;
            *(float2*)&P[(long)row * DM + col]       = make_float2(c[mt][nt][0], c[mt][nt][1]);
            *(float2*)&P[(long)(row + 8) * DM + col] = make_float2(c[mt][nt][2], c[mt][nt][3]);
        }
    }
}

__global__ __launch_bounds__(256) void add_out(float* __restrict__ out)
{
    int i = blockIdx.x * blockDim.x + threadIdx.x;
    if (i < NX4) {
        float4 a = ((const float4*)g_p0)[i];
        float4 b = ((const float4*)g_p1)[i];
        ((float4*)out)[i] = make_float4(a.x + b.x, a.y + b.y, a.z + b.z, a.w + b.w);
    }
}

// ============================================================================
// Flash attention: fp16 2-term (Q/P split 22-bit, K/V single 11-bit).
// cp.async double-buffered K/V (2 arrays/stage), LDSM, longest-qb first.
// BQ=128, BK=64. grid = (SEQ/128, NH, BATCH).
// ============================================================================
#define VS 36
#define ARR_U32 (64*VS)
#define STAGE_U32 (2*ARR_U32)
#define FL_SMEM (2*STAGE_U32*4)         // 36864 B

__global__ __launch_bounds__(256) void flash_mma()
{
    extern __shared__ __align__(16) uint32_t fsm[];
    const uint32_t smb = smem_u32(fsm);

    const int tid  = threadIdx.x;
    const int warp = tid >> 5, lane = tid & 31;
    const int g = lane >> 2, t = lane & 3;
    const int qb = gridDim.x - 1 - blockIdx.x;    // longest CTAs first
    const int h = blockIdx.y, b = blockIdx.z;
    const int q0 = qb * 128;
    const int headoff = h * DK;
    const long rowbase = (long)(b * SEQ + q0 + warp * 16);
    const long vtbase  = (long)((b * NH + h) * DK) * SEQ;
    const float NEG_INF = __int_as_float(0xff800000);

    const int f_row = ((lane >> 4) << 3) + (lane & 7);
    const int f_hk  = ((lane >> 3) & 1) * 4;

    const int jmax = 2 * (qb + 1);

    auto prefetch = [&](int jb, int stg) {
        const int ch = tid & 7;
#pragma unroll
        for (int u = 0; u < 4; u++) {
            int arr = u >> 1;                         // 0: K, 1: V^T
            int r2  = ((u & 1) << 5) + (tid >> 3);
            const uint16_t* src = (arr == 0)
                ? g_k  + (long)(b * SEQ + jb * 64 + r2) * DM + headoff + ch * 8
                : g_vt + vtbase + (long)r2 * SEQ + jb * 64 + ch * 8;
            uint32_t dst = smb + (uint32_t)(stg * STAGE_U32 + arr * ARR_U32 + r2 * VS) * 4 + ch * 16;
            CP16(dst, src);
        }
        CP_COMMIT();
    };

    prefetch(0, 0);   // overlap with Q fragment LDGs below

    // ---- Q fragments (scaled + split fp16) ----
    uint32_t qh[4][4], ql[4][4];
#pragma unroll
    for (int ks = 0; ks < 4; ks++) {
#pragma unroll
        for (int idx = 0; idx < 4; idx++) {
            int rr = (idx & 1) ? g + 8 : g;
            int d0 = ks * 16 + ((idx >> 1) ? 2 * t + 8 : 2 * t);
            long off = (rowbase + rr) * DM + headoff + d0;
            qh[ks][idx] = *(const uint32_t*)&g_qh[off];
            ql[ks][idx] = *(const uint32_t*)&g_ql[off];
        }
    }

    float m[2] = {NEG_INF, NEG_INF}, l[2] = {0.f, 0.f};
    float o[8][4];
#pragma unroll
    for (int dt = 0; dt < 8; dt++)
#pragma unroll
        for (int r = 0; r < 4; r++) o[dt][r] = 0.f;

    for (int jb = 0; jb < jmax; jb++) {
        const int stg = jb & 1;
        CP_WAIT0();
        __syncthreads();
        if (jb + 1 < jmax) prefetch(jb + 1, stg ^ 1);

        const uint32_t sK = smb + (uint32_t)(stg * STAGE_U32) * 4;
        const uint32_t sV = sK + ARR_U32 * 4;

        // ---- S = Q K^T: 16 MMAs (2 terms) ----
        float s[8][4];
#pragma unroll
        for (int nt = 0; nt < 8; nt++)
#pragma unroll
            for (int r = 0; r < 4; r++) s[nt][r] = 0.f;
#pragma unroll
        for (int ks = 0; ks < 4; ks++) {
            uint32_t kh[4][4];
#pragma unroll
            for (int p = 0; p < 4; p++) {
                uint32_t off = (uint32_t)((p * 16 + f_row) * VS + ks * 8 + f_hk) * 4;
                ldsm4(kh[p], sK + off);
            }
#pragma unroll
            for (int p = 0; p < 4; p++) {
                mma16816(s[2*p],   qh[ks], kh[p]);
                mma16816(s[2*p+1], qh[ks], kh[p] + 2);
            }
#pragma unroll
            for (int p = 0; p < 4; p++) {
                mma16816(s[2*p],   ql[ks], kh[p]);
                mma16816(s[2*p+1], ql[ks], kh[p] + 2);
            }
        }

        // ---- causal mask ----
        if (jb >= 2 * qb) {
#pragma unroll
            for (int nt = 0; nt < 8; nt++)
#pragma unroll
                for (int r = 0; r < 4; r++) {
                    int key = jb * 64 + nt * 8 + 2 * t + (r & 1);
                    int qr  = q0 + warp * 16 + g + ((r >> 1) ? 8 : 0);
                    if (key > qr) s[nt][r] = NEG_INF;
                }
        }

        // ---- online softmax ----
        float mx0 = NEG_INF, mx1 = NEG_INF;
#pragma unroll
        for (int nt = 0; nt < 8; nt++) {
            mx0 = fmaxf(mx0, fmaxf(s[nt][0], s[nt][1]));
            mx1 = fmaxf(mx1, fmaxf(s[nt][2], s[nt][3]));
        }
        mx0 = fmaxf(mx0, __shfl_xor_sync(0xffffffffu, mx0, 1));
        mx0 = fmaxf(mx0, __shfl_xor_sync(0xffffffffu, mx0, 2));
        mx1 = fmaxf(mx1, __shfl_xor_sync(0xffffffffu, mx1, 1));
        mx1 = fmaxf(mx1, __shfl_xor_sync(0xffffffffu, mx1, 2));
        float mn0 = fmaxf(m[0], mx0), mn1 = fmaxf(m[1], mx1);
        float al0 = __expf(m[0] - mn0), al1 = __expf(m[1] - mn1);
        m[0] = mn0; m[1] = mn1;
        float ps0 = 0.f, ps1 = 0.f;
#pragma unroll
        for (int nt = 0; nt < 8; nt++) {
            s[nt][0] = __expf(s[nt][0] - mn0); ps0 += s[nt][0];
            s[nt][1] = __expf(s[nt][1] - mn0); ps0 += s[nt][1];
            s[nt][2] = __expf(s[nt][2] - mn1); ps1 += s[nt][2];
            s[nt][3] = __expf(s[nt][3] - mn1); ps1 += s[nt][3];
        }
        ps0 += __shfl_xor_sync(0xffffffffu, ps0, 1);
        ps0 += __shfl_xor_sync(0xffffffffu, ps0, 2);
        ps1 += __shfl_xor_sync(0xffffffffu, ps1, 1);
        ps1 += __shfl_xor_sync(0xffffffffu, ps1, 2);
        l[0] = l[0] * al0 + ps0;
        l[1] = l[1] * al1 + ps1;
#pragma unroll
        for (int dt = 0; dt < 8; dt++) {
            o[dt][0] *= al0; o[dt][1] *= al0;
            o[dt][2] *= al1; o[dt][3] *= al1;
        }

        // ---- O += P V: 16 MMAs (P split 22-bit, V single) ----
#pragma unroll
        for (int kt = 0; kt < 4; kt++) {
            uint32_t ph[4], pl[4];
            ph[0] = hpack(s[2*kt][0],   s[2*kt][1]);
            ph[1] = hpack(s[2*kt][2],   s[2*kt][3]);
            ph[2] = hpack(s[2*kt+1][0], s[2*kt+1][1]);
            ph[3] = hpack(s[2*kt+1][2], s[2*kt+1][3]);
            pl[0] = hpack(s[2*kt][0]   - hlo(ph[0]), s[2*kt][1]   - hhi(ph[0]));
            pl[1] = hpack(s[2*kt][2]   - hlo(ph[1]), s[2*kt][3]   - hhi(ph[1]));
            pl[2] = hpack(s[2*kt+1][0] - hlo(ph[2]), s[2*kt+1][1] - hhi(ph[2]));
            pl[3] = hpack(s[2*kt+1][2] - hlo(ph[3]), s[2*kt+1][3] - hhi(ph[3]));
            uint32_t vh[4][4];
#pragma unroll
            for (int p = 0; p < 4; p++) {
                uint32_t off = (uint32_t)((p * 16 + f_row) * VS + kt * 8 + f_hk) * 4;
                ldsm4(vh[p], sV + off);
            }
#pragma unroll
            for (int p = 0; p < 4; p++) {
                mma16816(o[2*p],   ph, vh[p]);
                mma16816(o[2*p+1], ph, vh[p] + 2);
            }
#pragma unroll
            for (int p = 0; p < 4; p++) {
                mma16816(o[2*p],   pl, vh[p]);
                mma16816(o[2*p+1], pl, vh[p] + 2);
            }
        }
    }

    // ---- epilogue: write fp16 split for the output projection ----
    float inv0 = 1.f / l[0], inv1 = 1.f / l[1];
#pragma unroll
    for (int dt = 0; dt < 8; dt++) {
        int col = headoff + dt * 8 + 2 * t;
        float a0 = o[dt][0] * inv0, a1 = o[dt][1] * inv0;
        float a2 = o[dt][2] * inv1, a3 = o[dt][3] * inv1;
        uint32_t h0 = hpack(a0, a1), h1p = hpack(a2, a3);
        *(uint32_t*)&g_ah[(rowbase + g) * DM + col]     = h0;
        *(uint32_t*)&g_al[(rowbase + g) * DM + col]     = hpack(a0 - hlo(h0), a1 - hhi(h0));
        *(uint32_t*)&g_ah[(rowbase + g + 8) * DM + col] = h1p;
        *(uint32_t*)&g_al[(rowbase + g + 8) * DM + col] = hpack(a2 - hlo(h1p), a3 - hhi(h1p));
    }
}

// ---------------------------------------------------------------------------
extern "C" void kernel_launch(void* const* d_in, const int* in_sizes, int n_in,
                              void* d_out, int out_size)
{
    const float* x  = (const float*)d_in[0];
    const float* wq = (const float*)d_in[1];
    const float* wk = (const float*)d_in[2];
    const float* wv = (const float*)d_in[3];
    const float* wo = (const float*)d_in[4];
    float* out = (float*)d_out;

    cudaFuncSetAttribute(flash_mma,   cudaFuncAttributeMaxDynamicSharedMemorySize, FL_SMEM);
    cudaFuncSetAttribute(gemm_qkv,    cudaFuncAttributeMaxDynamicSharedMemorySize, G_SMEM);
    cudaFuncSetAttribute(gemm_out_sk, cudaFuncAttributeMaxDynamicSharedMemorySize, G_SMEM);

    const long ntot = NX4 + 4L * NW4;
    conv_all<<<(int)((ntot + 255) / 256), 256>>>(x, wq, wk, wv, wo);

    gemm_qkv<<<dim3(DM / 128, MROWS / 128, 3), 256, G_SMEM>>>();
    flash_mma<<<dim3(SEQ / 128, NH, BATCH), 256, FL_SMEM>>>();
    gemm_out_sk<<<dim3(DM / 128, MROWS / 128, 2), 256, G_SMEM>>>();
    add_out<<<(NX4 + 255) / 256, 256>>>(out);
}

// round 17
// speedup vs baseline: 1.8392x; 1.3032x over previous
#include <cuda_runtime.h>
#include <cuda_fp16.h>
#include <cstdint>

#define BATCH 2
#define SEQ   2048
#define DM    768
#define NH    12
#define DK    64
#define MROWS (BATCH*SEQ)

// Scratch (allocation-free rule: __device__ globals)
__device__ uint16_t g_xh[MROWS*DM], g_xl[MROWS*DM];   // x split (22-bit)
__device__ uint16_t g_q [MROWS*DM];                   // Q single fp16 (pre-scaled)
__device__ uint16_t g_k [MROWS*DM];                   // K single fp16 [token][d]
__device__ uint16_t g_vt[MROWS*DM];                   // V^T single fp16 [(b,h,dl)][token]
__device__ uint16_t g_a [MROWS*DM];                   // attention out single fp16
__device__ uint16_t g_wq[DM*DM], g_wk[DM*DM], g_wv[DM*DM], g_wo[DM*DM];
__device__ float g_p0[MROWS*DM], g_p1[MROWS*DM];      // split-K partials

// ============================================================================
// helpers
// ============================================================================
__device__ __forceinline__ uint32_t smem_u32(const void* p) {
    uint32_t a;
    asm("{ .reg .u64 t; cvta.to.shared.u64 t, %1; cvt.u32.u64 %0, t; }" : "=r"(a) : "l"(p));
    return a;
}
__device__ __forceinline__ uint32_t hpack(float x, float y) {
    __half2 h = __floats2half2_rn(x, y);
    return *(uint32_t*)&h;
}
__device__ __forceinline__ float hlo(uint32_t p) { __half2 h = *(__half2*)&p; return __low2float(h); }
__device__ __forceinline__ float hhi(uint32_t p) { __half2 h = *(__half2*)&p; return __high2float(h); }
__device__ __forceinline__ uint16_t h1(float x) { __half h = __float2half_rn(x); return *(uint16_t*)&h; }

__device__ __forceinline__ void mma16816(float* c, const uint32_t* a, const uint32_t* b) {
    asm volatile(
        "mma.sync.aligned.m16n8k16.row.col.f32.f16.f16.f32 "
        "{%0,%1,%2,%3}, {%4,%5,%6,%7}, {%8,%9}, {%0,%1,%2,%3};"
        : "+f"(c[0]), "+f"(c[1]), "+f"(c[2]), "+f"(c[3])
        : "r"(a[0]), "r"(a[1]), "r"(a[2]), "r"(a[3]), "r"(b[0]), "r"(b[1]));
}
__device__ __forceinline__ void ldsm4(uint32_t* r, uint32_t addr) {
    asm volatile("ldmatrix.sync.aligned.m8n8.x4.shared.b16 {%0,%1,%2,%3}, [%4];"
        : "=r"(r[0]), "=r"(r[1]), "=r"(r[2]), "=r"(r[3]) : "r"(addr));
}
#define CP16(dst, src) asm volatile("cp.async.ca.shared.global [%0], [%1], 16;" :: "r"(dst), "l"(src))
#define CP_COMMIT()    asm volatile("cp.async.commit_group;" ::: "memory")
#define CP_WAIT0()     asm volatile("cp.async.wait_group 0;" ::: "memory")

// ============================================================================
// Fused fp32 -> fp16 conversion: x split hi/lo, weights single fp16
// ============================================================================
#define NX4 (MROWS*DM/4)
#define NW4 (DM*DM/4)

__global__ __launch_bounds__(256) void conv_all(const float* __restrict__ x,
                                                const float* __restrict__ wq,
                                                const float* __restrict__ wk,
                                                const float* __restrict__ wv,
                                                const float* __restrict__ wo)
{
    long i = (long)blockIdx.x * blockDim.x + threadIdx.x;
    if (i < NX4) {
        float4 v = ((const float4*)x)[i];
        uint32_t h0 = hpack(v.x, v.y), h1p = hpack(v.z, v.w);
        ((uint2*)g_xh)[i] = make_uint2(h0, h1p);
        ((uint2*)g_xl)[i] = make_uint2(hpack(v.x - hlo(h0), v.y - hhi(h0)),
                                       hpack(v.z - hlo(h1p), v.w - hhi(h1p)));
        return;
    }
    long r = i - NX4;
    const float* src; uint16_t* dh; long j;
    if      (r < NW4)     { src = wq; dh = g_wq; j = r; }
    else if (r < 2*NW4)   { src = wk; dh = g_wk; j = r - NW4; }
    else if (r < 3*NW4)   { src = wv; dh = g_wv; j = r - 2*NW4; }
    else if (r < 4*NW4)   { src = wo; dh = g_wo; j = r - 3*NW4; }
    else return;
    float4 v = ((const float4*)src)[j];
    ((uint2*)dh)[j] = make_uint2(hpack(v.x, v.y), hpack(v.z, v.w));
}

// ============================================================================
// GEMM cores: SPLIT_A variant (x 22-bit, 2 MMAs/frag) and single-A (1 MMA/frag)
// ============================================================================
#define SROW 20
#define GST_U32 (128*SROW)

template<bool SPLIT_A>
__device__ __forceinline__ void gemm_core(const uint16_t* __restrict__ Agh,
                                          const uint16_t* __restrict__ Agl,
                                          const uint16_t* __restrict__ Bg,
                                          uint32_t smb, int m0, int n0,
                                          int kc0, int kc1,
                                          int tid, float c[4][4][4])
{
    const int NARR = SPLIT_A ? 3 : 2;
    const int warp = tid >> 5, lane = tid & 31;
    const int wm = warp >> 2, wn = warp & 3;
    const int a_row = lane & 15,                  a_hk = (lane >> 4) * 4;
    const int b_row = ((lane >> 4) << 3) + (lane & 7), b_hk = ((lane >> 3) & 1) * 4;

    auto pre = [&](int kc, int stg) {
#pragma unroll
        for (int u = 0; u < (SPLIT_A ? 6 : 4); u++) {
            int idx = tid + u * 256;
            int arr = idx >> 9, row = (idx >> 2) & 127, ch = idx & 3;
            const uint16_t* src;
            if (SPLIT_A) {
                if      (arr == 0) src = Agh + (long)(m0 + row) * DM + kc * 32 + ch * 8;
                else if (arr == 1) src = Agl + (long)(m0 + row) * DM + kc * 32 + ch * 8;
                else               src = Bg  + (long)(n0 + row) * DM + kc * 32 + ch * 8;
            } else {
                if (arr == 0) src = Agh + (long)(m0 + row) * DM + kc * 32 + ch * 8;
                else          src = Bg  + (long)(n0 + row) * DM + kc * 32 + ch * 8;
            }
            uint32_t dst = smb + (uint32_t)((stg * NARR + arr) * GST_U32 + row * SROW + ch * 4) * 4;
            CP16(dst, src);
        }
        CP_COMMIT();
    };

    pre(kc0, 0);

    for (int kc = kc0; kc < kc1; kc++) {
        const int stg = (kc - kc0) & 1;
        CP_WAIT0();
        __syncthreads();
        if (kc + 1 < kc1) pre(kc + 1, stg ^ 1);

        const uint32_t sAh = smb + (uint32_t)(stg * NARR * GST_U32) * 4;
        const uint32_t sAl = sAh + GST_U32 * 4;                       // valid iff SPLIT_A
        const uint32_t sB  = sAh + (uint32_t)(NARR - 1) * GST_U32 * 4;

#pragma unroll
        for (int ks = 0; ks < 2; ks++) {
            uint32_t bh[4][2];
#pragma unroll
            for (int p = 0; p < 2; p++) {
                uint32_t off = (uint32_t)((wn * 32 + p * 16 + b_row) * SROW + ks * 8 + b_hk) * 4;
                uint32_t rr[4];
                ldsm4(rr, sB + off);
                bh[2*p][0] = rr[0]; bh[2*p][1] = rr[1];
                bh[2*p+1][0] = rr[2]; bh[2*p+1][1] = rr[3];
            }
#pragma unroll
            for (int mt = 0; mt < 4; mt++) {
                uint32_t off = (uint32_t)((wm * 64 + mt * 16 + a_row) * SROW + ks * 8 + a_hk) * 4;
                uint32_t ah[4];
                ldsm4(ah, sAh + off);
#pragma unroll
                for (int nt = 0; nt < 4; nt++) mma16816(c[mt][nt], ah, bh[nt]);
                if (SPLIT_A) {
                    uint32_t al[4];
                    ldsm4(al, sAl + off);
#pragma unroll
                    for (int nt = 0; nt < 4; nt++) mma16816(c[mt][nt], al, bh[nt]);
                }
            }
        }
    }
}

#define G3_SMEM (2*3*GST_U32*4)        // 61440 B (split-A)
#define G2_SMEM (2*2*GST_U32*4)        // 40960 B (single-A)

// ============================================================================
// Fused QKV projection (x split; Q/K/V outputs single fp16)
// ============================================================================
__global__ __launch_bounds__(256, 2) void gemm_qkv()
{
    extern __shared__ __align__(16) uint32_t dsm[];
    const uint32_t smb = smem_u32(dsm);

    const int tid  = threadIdx.x;
    const int warp = tid >> 5, lane = tid & 31;
    const int g = lane >> 2, t = lane & 3;
    const int wm = warp >> 2, wn = warp & 3;
    const int m0 = blockIdx.y * 128, n0 = blockIdx.x * 128;
    const int z = blockIdx.z;
    const uint16_t* Bg = (z == 0) ? g_wq : ((z == 1) ? g_wk : g_wv);

    float c[4][4][4];
#pragma unroll
    for (int i = 0; i < 4; i++)
#pragma unroll
        for (int j = 0; j < 4; j++)
#pragma unroll
            for (int r = 0; r < 4; r++) c[i][j][r] = 0.f;

    gemm_core<true>(g_xh, g_xl, Bg, smb, m0, n0, 0, DM/32, tid, c);

    if (z < 2) {
        uint16_t* H = (z == 0) ? g_q : g_k;
        const float sc = (z == 0) ? 0.125f : 1.0f;
#pragma unroll
        for (int mt = 0; mt < 4; mt++) {
#pragma unroll
            for (int nt = 0; nt < 4; nt++) {
                int row = m0 + wm * 64 + mt * 16 + g;
                int col = n0 + wn * 32 + nt * 8 + 2 * t;
                *(uint32_t*)&H[(long)row * DM + col]       = hpack(c[mt][nt][0] * sc, c[mt][nt][1] * sc);
                *(uint32_t*)&H[(long)(row + 8) * DM + col] = hpack(c[mt][nt][2] * sc, c[mt][nt][3] * sc);
            }
        }
    } else {
        // V: transpose 128x128 tile via smem, single fp16 [(b,h,dl)][token]
        uint16_t* st = (uint16_t*)dsm;
        const int b = m0 / SEQ, s0 = m0 % SEQ;
        __syncthreads();
#pragma unroll
        for (int mt = 0; mt < 4; mt++)
#pragma unroll
            for (int nt = 0; nt < 4; nt++)
#pragma unroll
                for (int r = 0; r < 4; r++) {
                    int rowl = wm * 64 + mt * 16 + g + ((r >> 1) ? 8 : 0);
                    int coll = wn * 32 + nt * 8 + 2 * t + (r & 1);
                    st[coll * 136 + rowl] = h1(c[mt][nt][r]);
                }
        __syncthreads();
#pragma unroll
        for (int u = 0; u < 8; u++) {
            int idx = tid + u * 256;
            int dl128 = idx >> 4, ch = idx & 15;
            uint4 v = *(const uint4*)&st[dl128 * 136 + ch * 8];
            int colg = n0 + dl128;
            int hh = colg >> 6, dl = colg & 63;
            *(uint4*)&g_vt[((long)((b * NH + hh) * DK + dl)) * SEQ + s0 + ch * 8] = v;
        }
    }
}

// ============================================================================
// Output projection: single-A core, split-K2 + add
// ============================================================================
__global__ __launch_bounds__(256, 2) void gemm_out_sk()
{
    extern __shared__ __align__(16) uint32_t dsm[];
    const uint32_t smb = smem_u32(dsm);

    const int tid  = threadIdx.x;
    const int warp = tid >> 5, lane = tid & 31;
    const int g = lane >> 2, t = lane & 3;
    const int wm = warp >> 2, wn = warp & 3;
    const int m0 = blockIdx.y * 128, n0 = blockIdx.x * 128;
    const int z = blockIdx.z;
    float* P = z ? g_p1 : g_p0;

    float c[4][4][4];
#pragma unroll
    for (int i = 0; i < 4; i++)
#pragma unroll
        for (int j = 0; j < 4; j++)
#pragma unroll
            for (int r = 0; r < 4; r++) c[i][j][r] = 0.f;

    gemm_core<false>(g_a, nullptr, g_wo, smb, m0, n0, z * 12, (z + 1) * 12, tid, c);

#pragma unroll
    for (int mt = 0; mt < 4; mt++) {
#pragma unroll
        for (int nt = 0; nt < 4; nt++) {
            int row = m0 + wm * 64 + mt * 16 + g;
            int col = n0 + wn * 32 + nt * 8 + t * 2;
            *(float2*)&P[(long)row * DM + col]       = make_float2(c[mt][nt][0], c[mt][nt][1]);
            *(float2*)&P[(long)(row + 8) * DM + col] = make_float2(c[mt][nt][2], c[mt][nt][3]);
        }
    }
}

__global__ __launch_bounds__(256) void add_out(float* __restrict__ out)
{
    int i = blockIdx.x * blockDim.x + threadIdx.x;
    if (i < NX4) {
        float4 a = ((const float4*)g_p0)[i];
        float4 b = ((const float4*)g_p1)[i];
        ((float4*)out)[i] = make_float4(a.x + b.x, a.y + b.y, a.z + b.z, a.w + b.w);
    }
}

// ============================================================================
// Flash attention: all-single fp16 (Q, K, V, P). 64 MMAs/iter.
// cp.async double-buffered K/V, LDSM, longest-qb first.
// BQ=128, BK=64. grid = (SEQ/128, NH, BATCH).
// ============================================================================
#define VS 36
#define ARR_U32 (64*VS)
#define STAGE_U32 (2*ARR_U32)
#define FL_SMEM (2*STAGE_U32*4)         // 36864 B

__global__ __launch_bounds__(256) void flash_mma()
{
    extern __shared__ __align__(16) uint32_t fsm[];
    const uint32_t smb = smem_u32(fsm);

    const int tid  = threadIdx.x;
    const int warp = tid >> 5, lane = tid & 31;
    const int g = lane >> 2, t = lane & 3;
    const int qb = gridDim.x - 1 - blockIdx.x;    // longest CTAs first
    const int h = blockIdx.y, b = blockIdx.z;
    const int q0 = qb * 128;
    const int headoff = h * DK;
    const long rowbase = (long)(b * SEQ + q0 + warp * 16);
    const long vtbase  = (long)((b * NH + h) * DK) * SEQ;
    const float NEG_INF = __int_as_float(0xff800000);

    const int f_row = ((lane >> 4) << 3) + (lane & 7);
    const int f_hk  = ((lane >> 3) & 1) * 4;

    const int jmax = 2 * (qb + 1);

    auto prefetch = [&](int jb, int stg) {
        const int ch = tid & 7;
#pragma unroll
        for (int u = 0; u < 4; u++) {
            int arr = u >> 1;                         // 0: K, 1: V^T
            int r2  = ((u & 1) << 5) + (tid >> 3);
            const uint16_t* src = (arr == 0)
                ? g_k  + (long)(b * SEQ + jb * 64 + r2) * DM + headoff + ch * 8
                : g_vt + vtbase + (long)r2 * SEQ + jb * 64 + ch * 8;
            uint32_t dst = smb + (uint32_t)(stg * STAGE_U32 + arr * ARR_U32 + r2 * VS) * 4 + ch * 16;
            CP16(dst, src);
        }
        CP_COMMIT();
    };

    prefetch(0, 0);   // overlap with Q fragment LDGs below

    // ---- Q fragments (scaled, single fp16) ----
    uint32_t q[4][4];
#pragma unroll
    for (int ks = 0; ks < 4; ks++) {
#pragma unroll
        for (int idx = 0; idx < 4; idx++) {
            int rr = (idx & 1) ? g + 8 : g;
            int d0 = ks * 16 + ((idx >> 1) ? 2 * t + 8 : 2 * t);
            q[ks][idx] = *(const uint32_t*)&g_q[(rowbase + rr) * DM + headoff + d0];
        }
    }

    float m[2] = {NEG_INF, NEG_INF}, l[2] = {0.f, 0.f};
    float o[8][4];
#pragma unroll
    for (int dt = 0; dt < 8; dt++)
#pragma unroll
        for (int r = 0; r < 4; r++) o[dt][r] = 0.f;

    for (int jb = 0; jb < jmax; jb++) {
        const int stg = jb & 1;
        CP_WAIT0();
        __syncthreads();
        if (jb + 1 < jmax) prefetch(jb + 1, stg ^ 1);

        const uint32_t sK = smb + (uint32_t)(stg * STAGE_U32) * 4;
        const uint32_t sV = sK + ARR_U32 * 4;

        // ---- S = Q K^T: 32 MMAs ----
        float s[8][4];
#pragma unroll
        for (int nt = 0; nt < 8; nt++)
#pragma unroll
            for (int r = 0; r < 4; r++) s[nt][r] = 0.f;
#pragma unroll
        for (int ks = 0; ks < 4; ks++) {
            uint32_t kh[4][4];
#pragma unroll
            for (int p = 0; p < 4; p++) {
                uint32_t off = (uint32_t)((p * 16 + f_row) * VS + ks * 8 + f_hk) * 4;
                ldsm4(kh[p], sK + off);
            }
#pragma unroll
            for (int p = 0; p < 4; p++) {
                mma16816(s[2*p],   q[ks], kh[p]);
                mma16816(s[2*p+1], q[ks], kh[p] + 2);
            }
        }

        // ---- causal mask ----
        if (jb >= 2 * qb) {
#pragma unroll
            for (int nt = 0; nt < 8; nt++)
#pragma unroll
                for (int r = 0; r < 4; r++) {
                    int key = jb * 64 + nt * 8 + 2 * t + (r & 1);
                    int qr  = q0 + warp * 16 + g + ((r >> 1) ? 8 : 0);
                    if (key > qr) s[nt][r] = NEG_INF;
                }
        }

        // ---- online softmax ----
        float mx0 = NEG_INF, mx1 = NEG_INF;
#pragma unroll
        for (int nt = 0; nt < 8; nt++) {
            mx0 = fmaxf(mx0, fmaxf(s[nt][0], s[nt][1]));
            mx1 = fmaxf(mx1, fmaxf(s[nt][2], s[nt][3]));
        }
        mx0 = fmaxf(mx0, __shfl_xor_sync(0xffffffffu, mx0, 1));
        mx0 = fmaxf(mx0, __shfl_xor_sync(0xffffffffu, mx0, 2));
        mx1 = fmaxf(mx1, __shfl_xor_sync(0xffffffffu, mx1, 1));
        mx1 = fmaxf(mx1, __shfl_xor_sync(0xffffffffu, mx1, 2));
        float mn0 = fmaxf(m[0], mx0), mn1 = fmaxf(m[1], mx1);
        float al0 = __expf(m[0] - mn0), al1 = __expf(m[1] - mn1);
        m[0] = mn0; m[1] = mn1;
        float ps0 = 0.f, ps1 = 0.f;
#pragma unroll
        for (int nt = 0; nt < 8; nt++) {
            s[nt][0] = __expf(s[nt][0] - mn0); ps0 += s[nt][0];
            s[nt][1] = __expf(s[nt][1] - mn0); ps0 += s[nt][1];
            s[nt][2] = __expf(s[nt][2] - mn1); ps1 += s[nt][2];
            s[nt][3] = __expf(s[nt][3] - mn1); ps1 += s[nt][3];
        }
        ps0 += __shfl_xor_sync(0xffffffffu, ps0, 1);
        ps0 += __shfl_xor_sync(0xffffffffu, ps0, 2);
        ps1 += __shfl_xor_sync(0xffffffffu, ps1, 1);
        ps1 += __shfl_xor_sync(0xffffffffu, ps1, 2);
        l[0] = l[0] * al0 + ps0;
        l[1] = l[1] * al1 + ps1;
#pragma unroll
        for (int dt = 0; dt < 8; dt++) {
            o[dt][0] *= al0; o[dt][1] *= al0;
            o[dt][2] *= al1; o[dt][3] *= al1;
        }

        // ---- O += P V: 32 MMAs (P single fp16) ----
#pragma unroll
        for (int kt = 0; kt < 4; kt++) {
            uint32_t ph[4];
            ph[0] = hpack(s[2*kt][0],   s[2*kt][1]);
            ph[1] = hpack(s[2*kt][2],   s[2*kt][3]);
            ph[2] = hpack(s[2*kt+1][0], s[2*kt+1][1]);
            ph[3] = hpack(s[2*kt+1][2], s[2*kt+1][3]);
            uint32_t vh[4][4];
#pragma unroll
            for (int p = 0; p < 4; p++) {
                uint32_t off = (uint32_t)((p * 16 + f_row) * VS + kt * 8 + f_hk) * 4;
                ldsm4(vh[p], sV + off);
            }
#pragma unroll
            for (int p = 0; p < 4; p++) {
                mma16816(o[2*p],   ph, vh[p]);
                mma16816(o[2*p+1], ph, vh[p] + 2);
            }
        }
    }

    // ---- epilogue: write single fp16 for the output projection ----
    float inv0 = 1.f / l[0], inv1 = 1.f / l[1];
#pragma unroll
    for (int dt = 0; dt < 8; dt++) {
        int col = headoff + dt * 8 + 2 * t;
        *(uint32_t*)&g_a[(rowbase + g) * DM + col]     = hpack(o[dt][0] * inv0, o[dt][1] * inv0);
        *(uint32_t*)&g_a[(rowbase + g + 8) * DM + col] = hpack(o[dt][2] * inv1, o[dt][3] * inv1);
    }
}

// ---------------------------------------------------------------------------
extern "C" void kernel_launch(void* const* d_in, const int* in_sizes, int n_in,
                              void* d_out, int out_size)
{
    const float* x  = (const float*)d_in[0];
    const float* wq = (const float*)d_in[1];
    const float* wk = (const float*)d_in[2];
    const float* wv = (const float*)d_in[3];
    const float* wo = (const float*)d_in[4];
    float* out = (float*)d_out;

    cudaFuncSetAttribute(flash_mma,   cudaFuncAttributeMaxDynamicSharedMemorySize, FL_SMEM);
    cudaFuncSetAttribute(gemm_qkv,    cudaFuncAttributeMaxDynamicSharedMemorySize, G3_SMEM);
    cudaFuncSetAttribute(gemm_out_sk, cudaFuncAttributeMaxDynamicSharedMemorySize, G2_SMEM);

    const long ntot = NX4 + 4L * NW4;
    conv_all<<<(int)((ntot + 255) / 256), 256>>>(x, wq, wk, wv, wo);

    gemm_qkv<<<dim3(DM / 128, MROWS / 128, 3), 256, G3_SMEM>>>();
    flash_mma<<<dim3(SEQ / 128, NH, BATCH), 256, FL_SMEM>>>();
    gemm_out_sk<<<dim3(DM / 128, MROWS / 128, 2), 256, G2_SMEM>>>();
    add_out<<<(NX4 + 255) / 256, 256>>>(out);
}